// round 7
// baseline (speedup 1.0000x reference)
#include <cuda_runtime.h>
#include <math.h>
#include <cstdint>

#define B_   8
#define N_   3137
#define C_   768
#define H_   8
#define c_   96
#define IMG  56
#define QKVC 2304
#define M_   (B_*N_)      // 25096

#define NCHUNK 16
#define CHUNK  197
#define SPLITK 16
#define KVCHUNK 197

// ---------------- scratch (device globals: allocation-guard compliant) ------
__device__ float g_qkv[(size_t)M_*QKVC];          // 231 MB  q|k|v per token
__device__ float g_attn[(size_t)M_*C_];           // 77 MB   pre-proj
__device__ float g_kvpart[(size_t)SPLITK*B_*H_*c_*c_];
__device__ float g_kv[B_*H_*c_*c_];
__device__ float g_pmax[NCHUNK*B_*C_];
__device__ float g_psum[NCHUNK*B_*C_];
__device__ float g_smax[B_*C_];
__device__ float g_sinv[B_*C_];

// =====================  tf32 mma.sync GEMM: C = A @ W^T + bias  =============
// v3: BM=128, BN=128, BK=32, 128 threads = 4 warps (2m x 2n), warp tile 64x64.
// Fragment-dump smem layout with fully vectorized STS.128 staging.
//   A word  = ((kstep*8 + mtile)*32 + slotA)*4 + reg, slotA(l) = (l>>2) + (l&3)*8
//   B word  = (((kstep*16 + ntile)*2 + reg)*32 + lane)

__device__ __forceinline__ uint32_t f2tf(float f){
    uint32_t r; asm("cvt.rna.tf32.f32 %0, %1;" : "=r"(r) : "f"(f)); return r;
}

__device__ __forceinline__ void mma_tf32(float* c, const uint32_t* a, const uint32_t* b){
    asm volatile(
        "mma.sync.aligned.m16n8k8.row.col.f32.tf32.tf32.f32 "
        "{%0,%1,%2,%3}, {%4,%5,%6,%7}, {%8,%9}, {%0,%1,%2,%3};"
        : "+f"(c[0]), "+f"(c[1]), "+f"(c[2]), "+f"(c[3])
        : "r"(a[0]), "r"(a[1]), "r"(a[2]), "r"(a[3]), "r"(b[0]), "r"(b[1]));
}

#define GSTG 8192   // floats per stage: A 4096 + B 4096

__global__ __launch_bounds__(128, 2) void gemm_mma(
    const float* __restrict__ A, const float* __restrict__ W,
    const float* __restrict__ bias, float* __restrict__ C,
    int M, int N, int K)
{
    extern __shared__ float sm[];
    int tid = threadIdx.x, lane = tid & 31, wid = tid >> 5;
    int warp_m = wid & 1, warp_n = wid >> 1;
    int bm = blockIdx.y * 128, bn = blockIdx.x * 128;

    float acc[4][8][4];
#pragma unroll
    for (int i = 0; i < 4; i++)
#pragma unroll
        for (int j = 0; j < 8; j++)
#pragma unroll
            for (int r = 0; r < 4; r++) acc[i][j][r] = 0.f;

    // A units: u = tid + 128*iu (iu=0..1): g=u&7, kstep=(u>>3)&3, mtile=(u>>5)&7
    // B units: u = tid + 128*iu (iu=0..3): n8=u&7, kstep=(u>>3)&3, ntile=u>>5
    float4 ar[2][4];   // per A unit: row g (lo,hi k4), row g+8 (lo,hi k4)
    float4 br[4][2];   // per B unit: k4 lo, k4 hi

    auto ldg = [&](int t){
#pragma unroll
        for (int iu = 0; iu < 2; iu++) {
            int u = tid + iu * 128;
            int g = u & 7, kstep = (u >> 3) & 3, mtile = (u >> 5) & 7;
            int row0 = bm + mtile * 16 + g;
            const float* p = A + (size_t)row0 * K + t * 32 + kstep * 8;
            bool v0 = row0 < M, v1 = (row0 + 8) < M;
            ar[iu][0] = v0 ? *(const float4*)(p)     : make_float4(0,0,0,0);
            ar[iu][1] = v0 ? *(const float4*)(p + 4) : make_float4(0,0,0,0);
            ar[iu][2] = v1 ? *(const float4*)(p + (size_t)8 * K)     : make_float4(0,0,0,0);
            ar[iu][3] = v1 ? *(const float4*)(p + (size_t)8 * K + 4) : make_float4(0,0,0,0);
        }
#pragma unroll
        for (int iu = 0; iu < 4; iu++) {
            int u = tid + iu * 128;
            int n8 = u & 7, kstep = (u >> 3) & 3, ntile = u >> 5;
            const float* p = W + (size_t)(bn + ntile * 8 + n8) * K + t * 32 + kstep * 8;
            br[iu][0] = *(const float4*)(p);
            br[iu][1] = *(const float4*)(p + 4);
        }
    };
    auto sts = [&](int t){
        float* sA = sm + (t & 1) * GSTG;
        float* sB = sA + 4096;
#pragma unroll
        for (int iu = 0; iu < 2; iu++) {
            int u = tid + iu * 128;
            int g = u & 7, kstep = (u >> 3) & 3, mtile = (u >> 5) & 7;
            float f0[4] = {ar[iu][0].x, ar[iu][0].y, ar[iu][0].z, ar[iu][0].w};
            float f1[4] = {ar[iu][1].x, ar[iu][1].y, ar[iu][1].z, ar[iu][1].w};
            float f2[4] = {ar[iu][2].x, ar[iu][2].y, ar[iu][2].z, ar[iu][2].w};
            float f3[4] = {ar[iu][3].x, ar[iu][3].y, ar[iu][3].z, ar[iu][3].w};
            int base = (kstep * 8 + mtile) * 32;
#pragma unroll
            for (int cc = 0; cc < 4; cc++) {
                uint4 o;
                o.x = f2tf(f0[cc]);   // a0 = A[g][c]
                o.y = f2tf(f2[cc]);   // a1 = A[g+8][c]
                o.z = f2tf(f1[cc]);   // a2 = A[g][c+4]
                o.w = f2tf(f3[cc]);   // a3 = A[g+8][c+4]
                *(uint4*)&sA[(base + cc * 8 + g) * 4] = o;
            }
        }
#pragma unroll
        for (int iu = 0; iu < 4; iu++) {
            int u = tid + iu * 128;
            int n8 = u & 7, kstep = (u >> 3) & 3, ntile = u >> 5;
            int base = (kstep * 16 + ntile) * 2;
            uint4 o0, o1;
            o0.x = f2tf(br[iu][0].x); o0.y = f2tf(br[iu][0].y);
            o0.z = f2tf(br[iu][0].z); o0.w = f2tf(br[iu][0].w);
            o1.x = f2tf(br[iu][1].x); o1.y = f2tf(br[iu][1].y);
            o1.z = f2tf(br[iu][1].z); o1.w = f2tf(br[iu][1].w);
            *(uint4*)&sB[(base + 0) * 32 + n8 * 4] = o0;   // b0 for lanes n8*4..+3
            *(uint4*)&sB[(base + 1) * 32 + n8 * 4] = o1;   // b1 for lanes n8*4..+3
        }
    };
    int slotA = (lane >> 2) + (lane & 3) * 8;
    auto domma = [&](int t){
        const float* sA = sm + (t & 1) * GSTG;
        const float* sB = sA + 4096;
#pragma unroll
        for (int ks = 0; ks < 4; ks++) {
            uint4 a[4]; uint32_t b[8][2];
#pragma unroll
            for (int i = 0; i < 4; i++)
                a[i] = *(const uint4*)&sA[((ks * 8 + warp_m * 4 + i) * 32 + slotA) * 4];
#pragma unroll
            for (int j = 0; j < 8; j++) {
                int base = (ks * 16 + warp_n * 8 + j) * 2;
                b[j][0] = __float_as_uint(sB[(base + 0) * 32 + lane]);
                b[j][1] = __float_as_uint(sB[(base + 1) * 32 + lane]);
            }
#pragma unroll
            for (int i = 0; i < 4; i++)
#pragma unroll
                for (int j = 0; j < 8; j++)
                    mma_tf32(acc[i][j], (const uint32_t*)&a[i], b[j]);
        }
    };

    const int T = K / 32;
    ldg(0); sts(0);
    __syncthreads();

    for (int t = 0; t < T; t++) {
        if (t + 1 < T) ldg(t + 1);
        domma(t);
        if (t + 1 < T) sts(t + 1);
        __syncthreads();
    }

    // epilogue
    int g = lane >> 2, tg = lane & 3;
#pragma unroll
    for (int i = 0; i < 4; i++) {
        int row0 = bm + warp_m * 64 + i * 16 + g;
        int row1 = row0 + 8;
#pragma unroll
        for (int j = 0; j < 8; j++) {
            int col = bn + warp_n * 64 + j * 8 + tg * 2;
            float2 bv = *(const float2*)&bias[col];
            if (row0 < M) {
                float2 o = make_float2(acc[i][j][0] + bv.x, acc[i][j][1] + bv.y);
                *(float2*)(C + (size_t)row0 * N + col) = o;
            }
            if (row1 < M) {
                float2 o = make_float2(acc[i][j][2] + bv.x, acc[i][j][3] + bv.y);
                *(float2*)(C + (size_t)row1 * N + col) = o;
            }
        }
    }
}

// ---------------- softmax column stats over N (chunked, online) -------------
__global__ void k_stats_partial()
{
    int b = blockIdx.x, jg = blockIdx.y, ch = blockIdx.z;
    int j = jg*256 + threadIdx.x;
    int n0 = ch*CHUNK;
    int n1 = min(n0 + CHUNK, N_);
    const float* base = g_qkv + ((size_t)b*N_ + n0)*QKVC + C_ + j;
    float m = -1e30f, s = 0.f;
    for (int n = n0; n < n1; n++, base += QKVC) {
        float v = *base;
        if (v > m) { s = s*__expf(m - v) + 1.f; m = v; }
        else       { s += __expf(v - m); }
    }
    int col = b*C_ + j;
    g_pmax[ch*(B_*C_) + col] = m;
    g_psum[ch*(B_*C_) + col] = s;
}

__global__ void k_stats_combine()
{
    int col = blockIdx.x*256 + threadIdx.x;
    if (col >= B_*C_) return;
    float m = -1e30f;
#pragma unroll
    for (int ch = 0; ch < NCHUNK; ch++) m = fmaxf(m, g_pmax[ch*(B_*C_)+col]);
    float s = 0.f;
#pragma unroll
    for (int ch = 0; ch < NCHUNK; ch++) s += g_psum[ch*(B_*C_)+col]*__expf(g_pmax[ch*(B_*C_)+col]-m);
    g_smax[col] = m;
    g_sinv[col] = 1.f/s;
}

// ---------------- kv[b,h,c,d] = sum_n exp(k[n,c]-max[c]) * v[n,d] -----------
__global__ __launch_bounds__(256) void k_kv()
{
    int bh = blockIdx.x; int b = bh >> 3, h = bh & 7;
    int sk = blockIdx.y;
    int n0 = sk*KVCHUNK;
    int n1 = min(n0 + KVCHUNK, N_);

    __shared__ float Kb[2][16][96], Vb[2][16][96];
    __shared__ float smax[96];
    int tid = threadIdx.x;
    if (tid < 96) smax[tid] = g_smax[b*C_ + h*c_ + tid];
    __syncthreads();

    int tx = tid & 15, ty = tid >> 4;
    float acc[6][6];
#pragma unroll
    for (int i = 0; i < 6; i++)
#pragma unroll
        for (int j = 0; j < 6; j++) acc[i][j] = 0.f;

    int nt = (n1 - n0 + 15) >> 4;
    float4 r[3];

    auto ldg = [&](int t){
#pragma unroll
        for (int it = 0; it < 3; it++) {
            int idx = tid + it * 256;
            int rr = idx / 48, f = idx % 48;
            int n = n0 + t * 16 + rr;
            float4 v;
            if (n < n1) {
                const float* row = g_qkv + (size_t)(b*N_ + n)*QKVC;
                if (f < 24) v = *(const float4*)(row + C_ + h*c_ + f*4);
                else        v = *(const float4*)(row + 2*C_ + h*c_ + (f-24)*4);
            } else {
                float pad = (f < 24) ? -1e30f : 0.f;
                v = make_float4(pad, pad, pad, pad);
            }
            r[it] = v;
        }
    };
    auto sts = [&](int t){
        int buf = t & 1;
#pragma unroll
        for (int it = 0; it < 3; it++) {
            int idx = tid + it * 256;
            int rr = idx / 48, f = idx % 48;
            float4 v = r[it];
            if (f < 24) {
                int cc = f*4;
                float4 e;
                e.x = __expf(v.x - smax[cc+0]);
                e.y = __expf(v.y - smax[cc+1]);
                e.z = __expf(v.z - smax[cc+2]);
                e.w = __expf(v.w - smax[cc+3]);
                *(float4*)&Kb[buf][rr][cc] = e;
            } else {
                *(float4*)&Vb[buf][rr][(f-24)*4] = v;
            }
        }
    };

    ldg(0); sts(0);
    __syncthreads();

    for (int t = 0; t < nt; t++) {
        if (t + 1 < nt) ldg(t + 1);
        int buf = t & 1;
#pragma unroll
        for (int rr = 0; rr < 16; rr++) {
            float2 k0 = *(const float2*)&Kb[buf][rr][ty*6];
            float2 k1 = *(const float2*)&Kb[buf][rr][ty*6+2];
            float2 k2 = *(const float2*)&Kb[buf][rr][ty*6+4];
            float2 v0 = *(const float2*)&Vb[buf][rr][tx*6];
            float2 v1 = *(const float2*)&Vb[buf][rr][tx*6+2];
            float2 v2 = *(const float2*)&Vb[buf][rr][tx*6+4];
            float ka[6] = {k0.x,k0.y,k1.x,k1.y,k2.x,k2.y};
            float vb[6] = {v0.x,v0.y,v1.x,v1.y,v2.x,v2.y};
#pragma unroll
            for (int i = 0; i < 6; i++)
#pragma unroll
                for (int j = 0; j < 6; j++) acc[i][j] += ka[i]*vb[j];
        }
        if (t + 1 < nt) sts(t + 1);
        __syncthreads();
    }

    float* out = g_kvpart + ((size_t)sk*(B_*H_) + bh)*(c_*c_);
#pragma unroll
    for (int i = 0; i < 6; i++)
#pragma unroll
        for (int j = 0; j < 6; j++)
            out[(ty*6+i)*96 + tx*6 + j] = acc[i][j];
}

__global__ void k_kv_reduce()
{
    int i = blockIdx.x*256 + threadIdx.x;
    if (i >= B_*H_*c_*c_) return;
    int bh = i / (c_*c_);
    int rem = i - bh*(c_*c_);
    int cc = rem / c_;
    int b = bh >> 3, h = bh & 7;
    float s = 0.f;
#pragma unroll
    for (int sk = 0; sk < SPLITK; sk++)
        s += g_kvpart[((size_t)sk*(B_*H_) + bh)*(c_*c_) + rem];
    g_kv[i] = s * g_sinv[b*C_ + h*c_ + cc];
}

// ---------------- factor_att: g_attn = scale * q @ kv -----------------------
__global__ __launch_bounds__(256) void k_fact()
{
    extern __shared__ float smf[];
    float* kvs = smf;             // [96][96]
    float* qst = smf + 96*96;     // [96][132]

    int bh = blockIdx.x; int b = bh >> 3, h = bh & 7;
    int n0 = blockIdx.y * 128;
    int tid = threadIdx.x;

    for (int i = tid; i < 96*96; i += 256) kvs[i] = g_kv[(size_t)bh*(c_*c_) + i];
    for (int i = tid; i < 128*96; i += 256) {
        int rr = i / 96, j = i - rr*96;
        int n = n0 + rr;
        float q = 0.f;
        if (n < N_) q = g_qkv[((size_t)(b*N_+n))*QKVC + h*c_ + j];
        qst[j*132 + rr] = q;
    }
    __syncthreads();

    int tx = tid & 15, ty = tid >> 4;
    float acc[8][6];
#pragma unroll
    for (int i = 0; i < 8; i++)
#pragma unroll
        for (int j = 0; j < 6; j++) acc[i][j] = 0.f;

#pragma unroll 2
    for (int k = 0; k < 96; k++) {
        float4 q0 = *(const float4*)&qst[k*132 + ty*8];
        float4 q1 = *(const float4*)&qst[k*132 + ty*8 + 4];
        float2 b0 = *(const float2*)&kvs[k*96 + tx*6];
        float2 b1 = *(const float2*)&kvs[k*96 + tx*6 + 2];
        float2 b2 = *(const float2*)&kvs[k*96 + tx*6 + 4];
        float qa[8] = {q0.x,q0.y,q0.z,q0.w,q1.x,q1.y,q1.z,q1.w};
        float bb[6] = {b0.x,b0.y,b1.x,b1.y,b2.x,b2.y};
#pragma unroll
        for (int i = 0; i < 8; i++)
#pragma unroll
            for (int j = 0; j < 6; j++) acc[i][j] += qa[i]*bb[j];
    }

    const float scale = 0.10206207261596577f;
#pragma unroll
    for (int i = 0; i < 8; i++) {
        int n = n0 + ty*8 + i;
        if (n < N_) {
            float* o = g_attn + ((size_t)(b*N_+n))*C_ + h*c_ + tx*6;
            *(float2*)(o)   = make_float2(scale*acc[i][0], scale*acc[i][1]);
            *(float2*)(o+2) = make_float2(scale*acc[i][2], scale*acc[i][3]);
            *(float2*)(o+4) = make_float2(scale*acc[i][4], scale*acc[i][5]);
        }
    }
}

// ---------------- crpe: g_attn += q * (dwconv(v) + bias) --------------------
template <int KSZ>
__global__ __launch_bounds__(256) void k_crpe(const float* __restrict__ w,
                                              const float* __restrict__ bias,
                                              int ch_base)
{
    const int KK = KSZ*KSZ;
    int tile = blockIdx.x;
    int cg   = blockIdx.y;
    int b    = blockIdx.z;
    int ch0  = ch_base + cg*32;
    int ty0  = (tile/7)*8, tx0 = (tile%7)*8;

    __shared__ float wsm[32*49];
    __shared__ float bsm[32];
    __shared__ float patch[196][32];

    int tid = threadIdx.x;
    for (int i = tid; i < 32*KK; i += 256) {
        int chl = i / KK, wi = i - chl*KK;
        wsm[chl*KK + wi] = w[(cg*32 + chl)*KK + wi];
    }
    if (tid < 32) bsm[tid] = bias[cg*32 + tid];

    int lc = tid & 31, lp = tid >> 5;
    for (int p = lp; p < 196; p += 8) {
        int py = p/14 - 3 + ty0, px = p - (p/14)*14 - 3 + tx0;
        float v = 0.f;
        if ((unsigned)py < IMG && (unsigned)px < IMG)
            v = g_qkv[((size_t)(b*N_ + 1 + py*IMG + px))*QKVC + 2*C_ + ch0 + lc];
        patch[p][lc] = v;
    }
    __syncthreads();

    float wr[KK];
#pragma unroll
    for (int i = 0; i < KK; i++) wr[i] = wsm[lc*KK + i];
    float bval = bsm[lc];

    float acc[8];
#pragma unroll
    for (int i = 0; i < 8; i++) acc[i] = 0.f;

    const int pad = KSZ/2, off = 3 - pad;
#pragma unroll
    for (int dy = 0; dy < KSZ; dy++) {
        int prow = (lp + off + dy)*14;
        float r[KSZ + 7];
#pragma unroll
        for (int x = 0; x < KSZ + 7; x++) r[x] = patch[prow + off + x][lc];
#pragma unroll
        for (int ox = 0; ox < 8; ox++)
#pragma unroll
            for (int dx = 0; dx < KSZ; dx++)
                acc[ox] += r[ox+dx]*wr[dy*KSZ+dx];
    }

    int gy = ty0 + lp;
#pragma unroll
    for (int ox = 0; ox < 8; ox++) {
        int gx = tx0 + ox;
        size_t n = (size_t)b*N_ + 1 + gy*IMG + gx;
        float q = g_qkv[n*QKVC + ch0 + lc];
        g_attn[n*C_ + ch0 + lc] += q*(acc[ox] + bval);
    }
}

// ---------------- launch ----------------------------------------------------
extern "C" void kernel_launch(void* const* d_in, const int* in_sizes, int n_in,
                              void* d_out, int out_size)
{
    const float* x       = (const float*)d_in[0];
    const float* qkv_w   = (const float*)d_in[1];
    const float* qkv_b   = (const float*)d_in[2];
    const float* proj_w  = (const float*)d_in[3];
    const float* proj_b  = (const float*)d_in[4];
    const float* conv3_w = (const float*)d_in[5];
    const float* conv3_b = (const float*)d_in[6];
    const float* conv5_w = (const float*)d_in[7];
    const float* conv5_b = (const float*)d_in[8];
    const float* conv7_w = (const float*)d_in[9];
    const float* conv7_b = (const float*)d_in[10];

    float* qkv;  cudaGetSymbolAddress((void**)&qkv,  g_qkv);
    float* attn; cudaGetSymbolAddress((void**)&attn, g_attn);

    const int GEMM_SMEM = 2 * GSTG * sizeof(float);          // 64 KB
    const int FACT_SMEM = (96*96 + 96*132) * sizeof(float);  // ~85.5 KB

    static bool attr_set = false;
    if (!attr_set) {
        cudaFuncSetAttribute(k_fact, cudaFuncAttributeMaxDynamicSharedMemorySize, FACT_SMEM);
        cudaFuncSetAttribute(gemm_mma, cudaFuncAttributeMaxDynamicSharedMemorySize, GEMM_SMEM);
        attr_set = true;
    }

    // 1) qkv = x @ qkv_w^T + b   (tf32 mma.sync)
    gemm_mma<<<dim3(QKVC/128, (M_+127)/128), 128, GEMM_SMEM>>>(
        x, qkv_w, qkv_b, qkv, M_, QKVC, C_);

    // 2) softmax column stats over N
    k_stats_partial<<<dim3(B_, 3, NCHUNK), 256>>>();
    k_stats_combine<<<(B_*C_ + 255)/256, 256>>>();

    // 3) kv = k_softmax^T @ v   (split-K 16 + deterministic reduce)
    k_kv<<<dim3(B_*H_, SPLITK), 256>>>();
    k_kv_reduce<<<(B_*H_*c_*c_ + 255)/256, 256>>>();

    // 4) g_attn = scale * q @ kv
    k_fact<<<dim3(B_*H_, (N_+127)/128), 256, FACT_SMEM>>>();

    // 5) crpe: g_attn += q * dwconv(v)
    k_crpe<3><<<dim3(49, 6, B_), 256>>>(conv3_w, conv3_b, 0);
    k_crpe<5><<<dim3(49, 9, B_), 256>>>(conv5_w, conv5_b, 192);
    k_crpe<7><<<dim3(49, 9, B_), 256>>>(conv7_w, conv7_b, 480);

    // 6) out = attn @ proj_w^T + proj_b   (tf32 mma.sync)
    gemm_mma<<<dim3(C_/128, (M_+127)/128), 128, GEMM_SMEM>>>(
        attn, proj_w, proj_b, (float*)d_out, M_, C_, C_);
}

// round 10
// speedup vs baseline: 1.5444x; 1.5444x over previous
#include <cuda_runtime.h>
#include <math.h>
#include <cstdint>

#define B_   8
#define N_   3137
#define C_   768
#define H_   8
#define c_   96
#define IMG  56
#define QKVC 2304
#define M_   (B_*N_)      // 25096

#define NCHUNK 16
#define CHUNK  197
#define SPLITK 16
#define KVCHUNK 197

// ---------------- scratch (device globals: allocation-guard compliant) ------
__device__ float g_qkv[(size_t)M_*QKVC];          // 231 MB  q|k|v per token
__device__ float g_attn[(size_t)M_*C_];           // 77 MB   pre-proj
__device__ float g_kvpart[(size_t)SPLITK*B_*H_*c_*c_];
__device__ float g_kv[B_*H_*c_*c_];
__device__ float g_pmax[NCHUNK*B_*C_];
__device__ float g_psum[NCHUNK*B_*C_];
__device__ float g_smax[B_*C_];
__device__ float g_sinv[B_*C_];

// =====================  tf32 mma.sync GEMM: C = A @ W^T + bias  =============
// BM=128, BN=128, BK=32, 256 threads = 8 warps (2m x 4n), warp tile 64x32.
// R5's coalesced ldg + fragment-contiguous smem w/ kstep rotation,
// shrunk to 64KB smem so 2 blocks/SM run concurrently (2 barrier domains).

__device__ __forceinline__ uint32_t f2tf(float f){
    uint32_t r; asm("cvt.rna.tf32.f32 %0, %1;" : "=r"(r) : "f"(f)); return r;
}

__device__ __forceinline__ void mma_tf32(float* c, const uint32_t* a, const uint32_t* b){
    asm volatile(
        "mma.sync.aligned.m16n8k8.row.col.f32.tf32.tf32.f32 "
        "{%0,%1,%2,%3}, {%4,%5,%6,%7}, {%8,%9}, {%0,%1,%2,%3};"
        : "+f"(c[0]), "+f"(c[1]), "+f"(c[2]), "+f"(c[3])
        : "r"(a[0]), "r"(a[1]), "r"(a[2]), "r"(a[3]), "r"(b[0]), "r"(b[1]));
}

#define GSTG 8192   // floats per stage: A 4096 + B 4096

__global__ __launch_bounds__(256, 2) void gemm_mma(
    const float* __restrict__ A, const float* __restrict__ W,
    const float* __restrict__ bias, float* __restrict__ C,
    int M, int N, int K)
{
    extern __shared__ float sm[];
    int tid = threadIdx.x, lane = tid & 31, wid = tid >> 5;
    int warp_m = wid & 1, warp_n = wid >> 1;
    int bm = blockIdx.y * 128, bn = blockIdx.x * 128;

    float acc[4][4][4];
#pragma unroll
    for (int i = 0; i < 4; i++)
#pragma unroll
        for (int j = 0; j < 4; j++)
#pragma unroll
            for (int r = 0; r < 4; r++) acc[i][j][r] = 0.f;

    float4 ra[4], rb[4];

    auto ldg = [&](int t){
#pragma unroll
        for (int it = 0; it < 4; it++) {
            int idx = tid + it * 256;          // 0..1023
            int row = idx >> 3, kq = idx & 7;
            const float* ap = A + (size_t)(bm + row) * K + t * 32 + kq * 4;
            ra[it] = (bm + row < M) ? *(const float4*)ap : make_float4(0.f,0.f,0.f,0.f);
            rb[it] = *(const float4*)(W + (size_t)(bn + row) * K + t * 32 + kq * 4);
        }
    };
    auto sts = [&](int t){
        float* sA = sm + (t & 1) * GSTG;
        float* sB = sA + 4096;
#pragma unroll
        for (int it = 0; it < 4; it++) {
            int idx = tid + it * 256;
            int row = idx >> 3, kq = idx & 7;
            int kstep = kq >> 1, khi = kq & 1;
            // A fragment scatter
            int mtile = row >> 4, r16 = row & 15;
            int g = r16 & 7, hi = r16 >> 3;
            int baseA = (kstep * 8 + mtile) * 32;
            float va[4] = {ra[it].x, ra[it].y, ra[it].z, ra[it].w};
#pragma unroll
            for (int j = 0; j < 4; j++) {
                int slot = (g * 4 + j + kstep) & 31;
                sA[(baseA + slot) * 4 + khi * 2 + hi] = __uint_as_float(f2tf(va[j]));
            }
            // B fragment scatter
            int ntile = row >> 3, ng = row & 7;
            int baseB = (kstep * 16 + ntile) * 32;
            float vb[4] = {rb[it].x, rb[it].y, rb[it].z, rb[it].w};
#pragma unroll
            for (int j = 0; j < 4; j++) {
                int slot = (ng * 4 + j + kstep) & 31;
                sB[(baseB + slot) * 2 + khi] = __uint_as_float(f2tf(vb[j]));
            }
        }
    };
    auto domma = [&](int t){
        const float* sA = sm + (t & 1) * GSTG;
        const float* sB = sA + 4096;
#pragma unroll
        for (int ks = 0; ks < 4; ks++) {
            int rlane = (lane + ks) & 31;
            uint4 a[4]; uint2 b[4];
#pragma unroll
            for (int i = 0; i < 4; i++)
                a[i] = *(const uint4*)&sA[((ks * 8 + warp_m * 4 + i) * 32 + rlane) * 4];
#pragma unroll
            for (int j = 0; j < 4; j++)
                b[j] = *(const uint2*)&sB[((ks * 16 + warp_n * 4 + j) * 32 + rlane) * 2];
#pragma unroll
            for (int i = 0; i < 4; i++)
#pragma unroll
                for (int j = 0; j < 4; j++)
                    mma_tf32(acc[i][j], (const uint32_t*)&a[i], (const uint32_t*)&b[j]);
        }
    };

    const int T = K / 32;
    ldg(0); sts(0);
    __syncthreads();

    for (int t = 0; t < T; t++) {
        if (t + 1 < T) ldg(t + 1);
        domma(t);
        if (t + 1 < T) sts(t + 1);
        __syncthreads();
    }

    // epilogue
    int g = lane >> 2, tg = lane & 3;
#pragma unroll
    for (int i = 0; i < 4; i++) {
        int row0 = bm + warp_m * 64 + i * 16 + g;
        int row1 = row0 + 8;
#pragma unroll
        for (int j = 0; j < 4; j++) {
            int col = bn + warp_n * 32 + j * 8 + tg * 2;
            float2 bv = *(const float2*)&bias[col];
            if (row0 < M) {
                float2 o = make_float2(acc[i][j][0] + bv.x, acc[i][j][1] + bv.y);
                *(float2*)(C + (size_t)row0 * N + col) = o;
            }
            if (row1 < M) {
                float2 o = make_float2(acc[i][j][2] + bv.x, acc[i][j][3] + bv.y);
                *(float2*)(C + (size_t)row1 * N + col) = o;
            }
        }
    }
}

// ---------------- softmax column stats over N (chunked, online) -------------
__global__ void k_stats_partial()
{
    int b = blockIdx.x, jg = blockIdx.y, ch = blockIdx.z;
    int j = jg*256 + threadIdx.x;
    int n0 = ch*CHUNK;
    int n1 = min(n0 + CHUNK, N_);
    const float* base = g_qkv + ((size_t)b*N_ + n0)*QKVC + C_ + j;
    float m = -1e30f, s = 0.f;
    for (int n = n0; n < n1; n++, base += QKVC) {
        float v = *base;
        if (v > m) { s = s*__expf(m - v) + 1.f; m = v; }
        else       { s += __expf(v - m); }
    }
    int col = b*C_ + j;
    g_pmax[ch*(B_*C_) + col] = m;
    g_psum[ch*(B_*C_) + col] = s;
}

__global__ void k_stats_combine()
{
    int col = blockIdx.x*256 + threadIdx.x;
    if (col >= B_*C_) return;
    float m = -1e30f;
#pragma unroll
    for (int ch = 0; ch < NCHUNK; ch++) m = fmaxf(m, g_pmax[ch*(B_*C_)+col]);
    float s = 0.f;
#pragma unroll
    for (int ch = 0; ch < NCHUNK; ch++) s += g_psum[ch*(B_*C_)+col]*__expf(g_pmax[ch*(B_*C_)+col]-m);
    g_smax[col] = m;
    g_sinv[col] = 1.f/s;
}

// ---------------- kv[b,h,c,d] = sum_n exp(k[n,c]-max[c]) * v[n,d] -----------
__global__ __launch_bounds__(256) void k_kv()
{
    int bh = blockIdx.x; int b = bh >> 3, h = bh & 7;
    int sk = blockIdx.y;
    int n0 = sk*KVCHUNK;
    int n1 = min(n0 + KVCHUNK, N_);

    __shared__ float Kb[2][16][96], Vb[2][16][96];
    __shared__ float smax[96];
    int tid = threadIdx.x;
    if (tid < 96) smax[tid] = g_smax[b*C_ + h*c_ + tid];
    __syncthreads();

    int tx = tid & 15, ty = tid >> 4;
    float acc[6][6];
#pragma unroll
    for (int i = 0; i < 6; i++)
#pragma unroll
        for (int j = 0; j < 6; j++) acc[i][j] = 0.f;

    int nt = (n1 - n0 + 15) >> 4;
    float4 r[3];

    auto ldg = [&](int t){
#pragma unroll
        for (int it = 0; it < 3; it++) {
            int idx = tid + it * 256;
            int rr = idx / 48, f = idx % 48;
            int n = n0 + t * 16 + rr;
            float4 v;
            if (n < n1) {
                const float* row = g_qkv + (size_t)(b*N_ + n)*QKVC;
                if (f < 24) v = *(const float4*)(row + C_ + h*c_ + f*4);
                else        v = *(const float4*)(row + 2*C_ + h*c_ + (f-24)*4);
            } else {
                float pad = (f < 24) ? -1e30f : 0.f;
                v = make_float4(pad, pad, pad, pad);
            }
            r[it] = v;
        }
    };
    auto sts = [&](int t){
        int buf = t & 1;
#pragma unroll
        for (int it = 0; it < 3; it++) {
            int idx = tid + it * 256;
            int rr = idx / 48, f = idx % 48;
            float4 v = r[it];
            if (f < 24) {
                int cc = f*4;
                float4 e;
                e.x = __expf(v.x - smax[cc+0]);
                e.y = __expf(v.y - smax[cc+1]);
                e.z = __expf(v.z - smax[cc+2]);
                e.w = __expf(v.w - smax[cc+3]);
                *(float4*)&Kb[buf][rr][cc] = e;
            } else {
                *(float4*)&Vb[buf][rr][(f-24)*4] = v;
            }
        }
    };

    ldg(0); sts(0);
    __syncthreads();

    for (int t = 0; t < nt; t++) {
        if (t + 1 < nt) ldg(t + 1);
        int buf = t & 1;
#pragma unroll
        for (int rr = 0; rr < 16; rr++) {
            float2 k0 = *(const float2*)&Kb[buf][rr][ty*6];
            float2 k1 = *(const float2*)&Kb[buf][rr][ty*6+2];
            float2 k2 = *(const float2*)&Kb[buf][rr][ty*6+4];
            float2 v0 = *(const float2*)&Vb[buf][rr][tx*6];
            float2 v1 = *(const float2*)&Vb[buf][rr][tx*6+2];
            float2 v2 = *(const float2*)&Vb[buf][rr][tx*6+4];
            float ka[6] = {k0.x,k0.y,k1.x,k1.y,k2.x,k2.y};
            float vb[6] = {v0.x,v0.y,v1.x,v1.y,v2.x,v2.y};
#pragma unroll
            for (int i = 0; i < 6; i++)
#pragma unroll
                for (int j = 0; j < 6; j++) acc[i][j] += ka[i]*vb[j];
        }
        if (t + 1 < nt) sts(t + 1);
        __syncthreads();
    }

    float* out = g_kvpart + ((size_t)sk*(B_*H_) + bh)*(c_*c_);
#pragma unroll
    for (int i = 0; i < 6; i++)
#pragma unroll
        for (int j = 0; j < 6; j++)
            out[(ty*6+i)*96 + tx*6 + j] = acc[i][j];
}

__global__ void k_kv_reduce()
{
    int i = blockIdx.x*256 + threadIdx.x;
    if (i >= B_*H_*c_*c_) return;
    int bh = i / (c_*c_);
    int rem = i - bh*(c_*c_);
    int cc = rem / c_;
    int b = bh >> 3, h = bh & 7;
    float s = 0.f;
#pragma unroll
    for (int sk = 0; sk < SPLITK; sk++)
        s += g_kvpart[((size_t)sk*(B_*H_) + bh)*(c_*c_) + rem];
    g_kv[i] = s * g_sinv[b*C_ + h*c_ + cc];
}

// ---------------- factor_att: g_attn = scale * q @ kv -----------------------
__global__ __launch_bounds__(256) void k_fact()
{
    extern __shared__ float smf[];
    float* kvs = smf;             // [96][96]
    float* qst = smf + 96*96;     // [96][132]

    int bh = blockIdx.x; int b = bh >> 3, h = bh & 7;
    int n0 = blockIdx.y * 128;
    int tid = threadIdx.x;

    for (int i = tid; i < 96*96; i += 256) kvs[i] = g_kv[(size_t)bh*(c_*c_) + i];
    for (int i = tid; i < 128*96; i += 256) {
        int rr = i / 96, j = i - rr*96;
        int n = n0 + rr;
        float q = 0.f;
        if (n < N_) q = g_qkv[((size_t)(b*N_+n))*QKVC + h*c_ + j];
        qst[j*132 + rr] = q;
    }
    __syncthreads();

    int tx = tid & 15, ty = tid >> 4;
    float acc[8][6];
#pragma unroll
    for (int i = 0; i < 8; i++)
#pragma unroll
        for (int j = 0; j < 6; j++) acc[i][j] = 0.f;

#pragma unroll 2
    for (int k = 0; k < 96; k++) {
        float4 q0 = *(const float4*)&qst[k*132 + ty*8];
        float4 q1 = *(const float4*)&qst[k*132 + ty*8 + 4];
        float2 b0 = *(const float2*)&kvs[k*96 + tx*6];
        float2 b1 = *(const float2*)&kvs[k*96 + tx*6 + 2];
        float2 b2 = *(const float2*)&kvs[k*96 + tx*6 + 4];
        float qa[8] = {q0.x,q0.y,q0.z,q0.w,q1.x,q1.y,q1.z,q1.w};
        float bb[6] = {b0.x,b0.y,b1.x,b1.y,b2.x,b2.y};
#pragma unroll
        for (int i = 0; i < 8; i++)
#pragma unroll
            for (int j = 0; j < 6; j++) acc[i][j] += qa[i]*bb[j];
    }

    const float scale = 0.10206207261596577f;
#pragma unroll
    for (int i = 0; i < 8; i++) {
        int n = n0 + ty*8 + i;
        if (n < N_) {
            float* o = g_attn + ((size_t)(b*N_+n))*C_ + h*c_ + tx*6;
            *(float2*)(o)   = make_float2(scale*acc[i][0], scale*acc[i][1]);
            *(float2*)(o+2) = make_float2(scale*acc[i][2], scale*acc[i][3]);
            *(float2*)(o+4) = make_float2(scale*acc[i][4], scale*acc[i][5]);
        }
    }
}

// ---------------- crpe: g_attn += q * (dwconv(v) + bias) --------------------
template <int KSZ>
__global__ __launch_bounds__(256) void k_crpe(const float* __restrict__ w,
                                              const float* __restrict__ bias,
                                              int ch_base)
{
    const int KK = KSZ*KSZ;
    int tile = blockIdx.x;
    int cg   = blockIdx.y;
    int b    = blockIdx.z;
    int ch0  = ch_base + cg*32;
    int ty0  = (tile/7)*8, tx0 = (tile%7)*8;

    __shared__ float wsm[32*49];
    __shared__ float bsm[32];
    __shared__ float patch[196][32];

    int tid = threadIdx.x;
    for (int i = tid; i < 32*KK; i += 256) {
        int chl = i / KK, wi = i - chl*KK;
        wsm[chl*KK + wi] = w[(cg*32 + chl)*KK + wi];
    }
    if (tid < 32) bsm[tid] = bias[cg*32 + tid];

    int lc = tid & 31, lp = tid >> 5;
    for (int p = lp; p < 196; p += 8) {
        int py = p/14 - 3 + ty0, px = p - (p/14)*14 - 3 + tx0;
        float v = 0.f;
        if ((unsigned)py < IMG && (unsigned)px < IMG)
            v = g_qkv[((size_t)(b*N_ + 1 + py*IMG + px))*QKVC + 2*C_ + ch0 + lc];
        patch[p][lc] = v;
    }
    __syncthreads();

    float wr[KK];
#pragma unroll
    for (int i = 0; i < KK; i++) wr[i] = wsm[lc*KK + i];
    float bval = bsm[lc];

    float acc[8];
#pragma unroll
    for (int i = 0; i < 8; i++) acc[i] = 0.f;

    const int pad = KSZ/2, off = 3 - pad;
#pragma unroll
    for (int dy = 0; dy < KSZ; dy++) {
        int prow = (lp + off + dy)*14;
        float r[KSZ + 7];
#pragma unroll
        for (int x = 0; x < KSZ + 7; x++) r[x] = patch[prow + off + x][lc];
#pragma unroll
        for (int ox = 0; ox < 8; ox++)
#pragma unroll
            for (int dx = 0; dx < KSZ; dx++)
                acc[ox] += r[ox+dx]*wr[dy*KSZ+dx];
    }

    int gy = ty0 + lp;
#pragma unroll
    for (int ox = 0; ox < 8; ox++) {
        int gx = tx0 + ox;
        size_t n = (size_t)b*N_ + 1 + gy*IMG + gx;
        float q = g_qkv[n*QKVC + ch0 + lc];
        g_attn[n*C_ + ch0 + lc] += q*(acc[ox] + bval);
    }
}

// ---------------- launch ----------------------------------------------------
extern "C" void kernel_launch(void* const* d_in, const int* in_sizes, int n_in,
                              void* d_out, int out_size)
{
    const float* x       = (const float*)d_in[0];
    const float* qkv_w   = (const float*)d_in[1];
    const float* qkv_b   = (const float*)d_in[2];
    const float* proj_w  = (const float*)d_in[3];
    const float* proj_b  = (const float*)d_in[4];
    const float* conv3_w = (const float*)d_in[5];
    const float* conv3_b = (const float*)d_in[6];
    const float* conv5_w = (const float*)d_in[7];
    const float* conv5_b = (const float*)d_in[8];
    const float* conv7_w = (const float*)d_in[9];
    const float* conv7_b = (const float*)d_in[10];

    float* qkv;  cudaGetSymbolAddress((void**)&qkv,  g_qkv);
    float* attn; cudaGetSymbolAddress((void**)&attn, g_attn);

    const int GEMM_SMEM = 2 * GSTG * sizeof(float);          // 64 KB
    const int FACT_SMEM = (96*96 + 96*132) * sizeof(float);  // ~85.5 KB

    static bool attr_set = false;
    if (!attr_set) {
        cudaFuncSetAttribute(k_fact, cudaFuncAttributeMaxDynamicSharedMemorySize, FACT_SMEM);
        cudaFuncSetAttribute(gemm_mma, cudaFuncAttributeMaxDynamicSharedMemorySize, GEMM_SMEM);
        attr_set = true;
    }

    // 1) qkv = x @ qkv_w^T + b   (tf32 mma.sync)
    gemm_mma<<<dim3(QKVC/128, (M_+127)/128), 256, GEMM_SMEM>>>(
        x, qkv_w, qkv_b, qkv, M_, QKVC, C_);

    // 2) softmax column stats over N
    k_stats_partial<<<dim3(B_, 3, NCHUNK), 256>>>();
    k_stats_combine<<<(B_*C_ + 255)/256, 256>>>();

    // 3) kv = k_softmax^T @ v   (split-K 16 + deterministic reduce)
    k_kv<<<dim3(B_*H_, SPLITK), 256>>>();
    k_kv_reduce<<<(B_*H_*c_*c_ + 255)/256, 256>>>();

    // 4) g_attn = scale * q @ kv
    k_fact<<<dim3(B_*H_, (N_+127)/128), 256, FACT_SMEM>>>();

    // 5) crpe: g_attn += q * dwconv(v)
    k_crpe<3><<<dim3(49, 6, B_), 256>>>(conv3_w, conv3_b, 0);
    k_crpe<5><<<dim3(49, 9, B_), 256>>>(conv5_w, conv5_b, 192);
    k_crpe<7><<<dim3(49, 9, B_), 256>>>(conv7_w, conv7_b, 480);

    // 6) out = attn @ proj_w^T + proj_b   (tf32 mma.sync)
    gemm_mma<<<dim3(C_/128, (M_+127)/128), 256, GEMM_SMEM>>>(
        attn, proj_w, proj_b, (float*)d_out, M_, C_, C_);
}

// round 11
// speedup vs baseline: 1.8984x; 1.2293x over previous
#include <cuda_runtime.h>
#include <cuda_fp16.h>
#include <math.h>
#include <cstdint>

#define B_   8
#define N_   3137
#define C_   768
#define H_   8
#define c_   96
#define IMG  56
#define QKVC 2304
#define M_   (B_*N_)      // 25096

#define NCHUNK 16
#define CHUNK  197
#define SPLITK 16
#define KVCHUNK 197

// ---------------- scratch (device globals: allocation-guard compliant) ------
__device__ float g_qkv[(size_t)M_*QKVC];          // 231 MB  q|k|v per token
__device__ float g_attn[(size_t)M_*C_];           // 77 MB   pre-proj
__device__ float g_kvpart[(size_t)SPLITK*B_*H_*c_*c_];
__device__ float g_kv[B_*H_*c_*c_];
__device__ float g_pmax[NCHUNK*B_*C_];
__device__ float g_psum[NCHUNK*B_*C_];
__device__ float g_smax[B_*C_];
__device__ float g_sinv[B_*C_];

// =====================  fp16 mma.sync GEMM: C = A @ W^T + bias  =============
// BM=128, BN=256, BK=32, 256 threads = 8 warps (2m x 4n), warp tile 64x64.
// Row-major half tiles (64B rows) with 16B-unit XOR swizzle; ldmatrix.x4
// fragment loads; mma.m16n8k16.f32.f16.f16.f32 (same mantissa as tf32).

__device__ __forceinline__ uint32_t smem_u32(const void* p){
    uint32_t a;
    asm("{ .reg .u64 t; cvta.to.shared.u64 t, %1; cvt.u32.u64 %0, t; }" : "=r"(a) : "l"(p));
    return a;
}
__device__ __forceinline__ void ldsm_x4(uint32_t* r, uint32_t addr){
    asm volatile("ldmatrix.sync.aligned.m8n8.x4.shared.b16 {%0,%1,%2,%3}, [%4];"
        : "=r"(r[0]), "=r"(r[1]), "=r"(r[2]), "=r"(r[3]) : "r"(addr));
}
__device__ __forceinline__ void mma_f16(float* c, const uint32_t* a, const uint32_t* b){
    asm volatile(
        "mma.sync.aligned.m16n8k16.row.col.f32.f16.f16.f32 "
        "{%0,%1,%2,%3}, {%4,%5,%6,%7}, {%8,%9}, {%0,%1,%2,%3};"
        : "+f"(c[0]), "+f"(c[1]), "+f"(c[2]), "+f"(c[3])
        : "r"(a[0]), "r"(a[1]), "r"(a[2]), "r"(a[3]), "r"(b[0]), "r"(b[1]));
}
// swizzled byte offset inside a [rows][32 half] tile (64B rows, 16B units)
__device__ __forceinline__ uint32_t swz(int row, int unit, int lo8){
    return (uint32_t)(row * 64 + ((unit ^ ((row >> 1) & 3)) << 4) + lo8);
}

#define STAGE_BYTES 24576   // A 8KB + B 16KB per stage

__global__ __launch_bounds__(256, 1) void gemm_hmma(
    const float* __restrict__ A, const float* __restrict__ W,
    const float* __restrict__ bias, float* __restrict__ C,
    int M, int N, int K)
{
    extern __shared__ char smc[];
    int tid = threadIdx.x, lane = tid & 31, wid = tid >> 5;
    int warp_m = wid & 1, warp_n = wid >> 1;
    int bm = blockIdx.y * 128, bn = blockIdx.x * 256;

    float acc[4][8][4];
#pragma unroll
    for (int i = 0; i < 4; i++)
#pragma unroll
        for (int j = 0; j < 8; j++)
#pragma unroll
            for (int r = 0; r < 4; r++) acc[i][j][r] = 0.f;

    uint2 ra[4], rb[8];   // 4 halfs each (converted at ldg time)

    auto ldg = [&](int t){
#pragma unroll
        for (int it = 0; it < 4; it++) {
            int idx = tid + it * 256;          // 0..1023
            int row = idx >> 3, kq = idx & 7;
            const float* ap = A + (size_t)(bm + row) * K + t * 32 + kq * 4;
            float4 v = (bm + row < M) ? *(const float4*)ap : make_float4(0.f,0.f,0.f,0.f);
            __half2 h0 = __floats2half2_rn(v.x, v.y);
            __half2 h1 = __floats2half2_rn(v.z, v.w);
            ra[it].x = *(uint32_t*)&h0; ra[it].y = *(uint32_t*)&h1;
        }
#pragma unroll
        for (int it = 0; it < 8; it++) {
            int idx = tid + it * 256;          // 0..2047
            int row = idx >> 3, kq = idx & 7;
            float4 v = *(const float4*)(W + (size_t)(bn + row) * K + t * 32 + kq * 4);
            __half2 h0 = __floats2half2_rn(v.x, v.y);
            __half2 h1 = __floats2half2_rn(v.z, v.w);
            rb[it].x = *(uint32_t*)&h0; rb[it].y = *(uint32_t*)&h1;
        }
    };
    auto sts = [&](int t){
        char* sA = smc + (t & 1) * STAGE_BYTES;
        char* sB = sA + 8192;
#pragma unroll
        for (int it = 0; it < 4; it++) {
            int idx = tid + it * 256;
            int row = idx >> 3, kq = idx & 7;
            *(uint2*)(sA + swz(row, kq >> 1, (kq & 1) * 8)) = ra[it];
        }
#pragma unroll
        for (int it = 0; it < 8; it++) {
            int idx = tid + it * 256;
            int row = idx >> 3, kq = idx & 7;
            *(uint2*)(sB + swz(row, kq >> 1, (kq & 1) * 8)) = rb[it];
        }
    };
    auto domma = [&](int t){
        uint32_t saA = smem_u32(smc) + (t & 1) * STAGE_BYTES;
        uint32_t saB = saA + 8192;
        int bblk = lane >> 3, rr = lane & 7;
#pragma unroll
        for (int ks = 0; ks < 2; ks++) {
            uint32_t a[4][4], b[4][4];
#pragma unroll
            for (int i = 0; i < 4; i++) {
                int mtile = warp_m * 4 + i;
                int row = mtile * 16 + (bblk & 1) * 8 + rr;
                int u = ks * 2 + (bblk >> 1);
                ldsm_x4(a[i], saA + swz(row, u, 0));
            }
#pragma unroll
            for (int j2 = 0; j2 < 4; j2++) {
                int nt = warp_n * 8 + j2 * 2 + (lane >> 4);
                int kblk = (lane >> 3) & 1;
                int row = nt * 8 + rr;
                int u = ks * 2 + kblk;
                ldsm_x4(b[j2], saB + swz(row, u, 0));
            }
#pragma unroll
            for (int i = 0; i < 4; i++)
#pragma unroll
                for (int j2 = 0; j2 < 4; j2++) {
                    mma_f16(acc[i][j2*2+0], a[i], &b[j2][0]);
                    mma_f16(acc[i][j2*2+1], a[i], &b[j2][2]);
                }
        }
    };

    const int T = K / 32;
    ldg(0); sts(0);
    __syncthreads();

    for (int t = 0; t < T; t++) {
        if (t + 1 < T) ldg(t + 1);
        domma(t);
        if (t + 1 < T) sts(t + 1);
        __syncthreads();
    }

    // epilogue
    int g = lane >> 2, tg = lane & 3;
#pragma unroll
    for (int i = 0; i < 4; i++) {
        int row0 = bm + warp_m * 64 + i * 16 + g;
        int row1 = row0 + 8;
#pragma unroll
        for (int j = 0; j < 8; j++) {
            int col = bn + warp_n * 64 + j * 8 + tg * 2;
            float2 bv = *(const float2*)&bias[col];
            if (row0 < M) {
                float2 o = make_float2(acc[i][j][0] + bv.x, acc[i][j][1] + bv.y);
                *(float2*)(C + (size_t)row0 * N + col) = o;
            }
            if (row1 < M) {
                float2 o = make_float2(acc[i][j][2] + bv.x, acc[i][j][3] + bv.y);
                *(float2*)(C + (size_t)row1 * N + col) = o;
            }
        }
    }
}

// ---------------- softmax column stats over N (chunked, online) -------------
__global__ void k_stats_partial()
{
    int b = blockIdx.x, jg = blockIdx.y, ch = blockIdx.z;
    int j = jg*256 + threadIdx.x;
    int n0 = ch*CHUNK;
    int n1 = min(n0 + CHUNK, N_);
    const float* base = g_qkv + ((size_t)b*N_ + n0)*QKVC + C_ + j;
    float m = -1e30f, s = 0.f;
    for (int n = n0; n < n1; n++, base += QKVC) {
        float v = *base;
        if (v > m) { s = s*__expf(m - v) + 1.f; m = v; }
        else       { s += __expf(v - m); }
    }
    int col = b*C_ + j;
    g_pmax[ch*(B_*C_) + col] = m;
    g_psum[ch*(B_*C_) + col] = s;
}

__global__ void k_stats_combine()
{
    int col = blockIdx.x*256 + threadIdx.x;
    if (col >= B_*C_) return;
    float m = -1e30f;
#pragma unroll
    for (int ch = 0; ch < NCHUNK; ch++) m = fmaxf(m, g_pmax[ch*(B_*C_)+col]);
    float s = 0.f;
#pragma unroll
    for (int ch = 0; ch < NCHUNK; ch++) s += g_psum[ch*(B_*C_)+col]*__expf(g_pmax[ch*(B_*C_)+col]-m);
    g_smax[col] = m;
    g_sinv[col] = 1.f/s;
}

// ---------------- kv[b,h,c,d] = sum_n exp(k[n,c]-max[c]) * v[n,d] -----------
__global__ __launch_bounds__(256) void k_kv()
{
    int bh = blockIdx.x; int b = bh >> 3, h = bh & 7;
    int sk = blockIdx.y;
    int n0 = sk*KVCHUNK;
    int n1 = min(n0 + KVCHUNK, N_);

    __shared__ float Kb[2][16][96], Vb[2][16][96];
    __shared__ float smax[96];
    int tid = threadIdx.x;
    if (tid < 96) smax[tid] = g_smax[b*C_ + h*c_ + tid];
    __syncthreads();

    int tx = tid & 15, ty = tid >> 4;
    float acc[6][6];
#pragma unroll
    for (int i = 0; i < 6; i++)
#pragma unroll
        for (int j = 0; j < 6; j++) acc[i][j] = 0.f;

    int nt = (n1 - n0 + 15) >> 4;
    float4 r[3];

    auto ldg = [&](int t){
#pragma unroll
        for (int it = 0; it < 3; it++) {
            int idx = tid + it * 256;
            int rr = idx / 48, f = idx % 48;
            int n = n0 + t * 16 + rr;
            float4 v;
            if (n < n1) {
                const float* row = g_qkv + (size_t)(b*N_ + n)*QKVC;
                if (f < 24) v = *(const float4*)(row + C_ + h*c_ + f*4);
                else        v = *(const float4*)(row + 2*C_ + h*c_ + (f-24)*4);
            } else {
                float pad = (f < 24) ? -1e30f : 0.f;
                v = make_float4(pad, pad, pad, pad);
            }
            r[it] = v;
        }
    };
    auto sts = [&](int t){
        int buf = t & 1;
#pragma unroll
        for (int it = 0; it < 3; it++) {
            int idx = tid + it * 256;
            int rr = idx / 48, f = idx % 48;
            float4 v = r[it];
            if (f < 24) {
                int cc = f*4;
                float4 e;
                e.x = __expf(v.x - smax[cc+0]);
                e.y = __expf(v.y - smax[cc+1]);
                e.z = __expf(v.z - smax[cc+2]);
                e.w = __expf(v.w - smax[cc+3]);
                *(float4*)&Kb[buf][rr][cc] = e;
            } else {
                *(float4*)&Vb[buf][rr][(f-24)*4] = v;
            }
        }
    };

    ldg(0); sts(0);
    __syncthreads();

    for (int t = 0; t < nt; t++) {
        if (t + 1 < nt) ldg(t + 1);
        int buf = t & 1;
#pragma unroll
        for (int rr = 0; rr < 16; rr++) {
            float2 k0 = *(const float2*)&Kb[buf][rr][ty*6];
            float2 k1 = *(const float2*)&Kb[buf][rr][ty*6+2];
            float2 k2 = *(const float2*)&Kb[buf][rr][ty*6+4];
            float2 v0 = *(const float2*)&Vb[buf][rr][tx*6];
            float2 v1 = *(const float2*)&Vb[buf][rr][tx*6+2];
            float2 v2 = *(const float2*)&Vb[buf][rr][tx*6+4];
            float ka[6] = {k0.x,k0.y,k1.x,k1.y,k2.x,k2.y};
            float vb[6] = {v0.x,v0.y,v1.x,v1.y,v2.x,v2.y};
#pragma unroll
            for (int i = 0; i < 6; i++)
#pragma unroll
                for (int j = 0; j < 6; j++) acc[i][j] += ka[i]*vb[j];
        }
        if (t + 1 < nt) sts(t + 1);
        __syncthreads();
    }

    float* out = g_kvpart + ((size_t)sk*(B_*H_) + bh)*(c_*c_);
#pragma unroll
    for (int i = 0; i < 6; i++)
#pragma unroll
        for (int j = 0; j < 6; j++)
            out[(ty*6+i)*96 + tx*6 + j] = acc[i][j];
}

__global__ void k_kv_reduce()
{
    int i = blockIdx.x*256 + threadIdx.x;
    if (i >= B_*H_*c_*c_) return;
    int bh = i / (c_*c_);
    int rem = i - bh*(c_*c_);
    int cc = rem / c_;
    int b = bh >> 3, h = bh & 7;
    float s = 0.f;
#pragma unroll
    for (int sk = 0; sk < SPLITK; sk++)
        s += g_kvpart[((size_t)sk*(B_*H_) + bh)*(c_*c_) + rem];
    g_kv[i] = s * g_sinv[b*C_ + h*c_ + cc];
}

// ---------------- factor_att: g_attn = scale * q @ kv -----------------------
__global__ __launch_bounds__(256) void k_fact()
{
    extern __shared__ float smf[];
    float* kvs = smf;             // [96][96]
    float* qst = smf + 96*96;     // [96][132]

    int bh = blockIdx.x; int b = bh >> 3, h = bh & 7;
    int n0 = blockIdx.y * 128;
    int tid = threadIdx.x;

    for (int i = tid; i < 96*96; i += 256) kvs[i] = g_kv[(size_t)bh*(c_*c_) + i];
    for (int i = tid; i < 128*96; i += 256) {
        int rr = i / 96, j = i - rr*96;
        int n = n0 + rr;
        float q = 0.f;
        if (n < N_) q = g_qkv[((size_t)(b*N_+n))*QKVC + h*c_ + j];
        qst[j*132 + rr] = q;
    }
    __syncthreads();

    int tx = tid & 15, ty = tid >> 4;
    float acc[8][6];
#pragma unroll
    for (int i = 0; i < 8; i++)
#pragma unroll
        for (int j = 0; j < 6; j++) acc[i][j] = 0.f;

#pragma unroll 2
    for (int k = 0; k < 96; k++) {
        float4 q0 = *(const float4*)&qst[k*132 + ty*8];
        float4 q1 = *(const float4*)&qst[k*132 + ty*8 + 4];
        float2 b0 = *(const float2*)&kvs[k*96 + tx*6];
        float2 b1 = *(const float2*)&kvs[k*96 + tx*6 + 2];
        float2 b2 = *(const float2*)&kvs[k*96 + tx*6 + 4];
        float qa[8] = {q0.x,q0.y,q0.z,q0.w,q1.x,q1.y,q1.z,q1.w};
        float bb[6] = {b0.x,b0.y,b1.x,b1.y,b2.x,b2.y};
#pragma unroll
        for (int i = 0; i < 8; i++)
#pragma unroll
            for (int j = 0; j < 6; j++) acc[i][j] += qa[i]*bb[j];
    }

    const float scale = 0.10206207261596577f;
#pragma unroll
    for (int i = 0; i < 8; i++) {
        int n = n0 + ty*8 + i;
        if (n < N_) {
            float* o = g_attn + ((size_t)(b*N_+n))*C_ + h*c_ + tx*6;
            *(float2*)(o)   = make_float2(scale*acc[i][0], scale*acc[i][1]);
            *(float2*)(o+2) = make_float2(scale*acc[i][2], scale*acc[i][3]);
            *(float2*)(o+4) = make_float2(scale*acc[i][4], scale*acc[i][5]);
        }
    }
}

// ---------------- crpe: g_attn += q * (dwconv(v) + bias) --------------------
template <int KSZ>
__global__ __launch_bounds__(256) void k_crpe(const float* __restrict__ w,
                                              const float* __restrict__ bias,
                                              int ch_base)
{
    const int KK = KSZ*KSZ;
    int tile = blockIdx.x;
    int cg   = blockIdx.y;
    int b    = blockIdx.z;
    int ch0  = ch_base + cg*32;
    int ty0  = (tile/7)*8, tx0 = (tile%7)*8;

    __shared__ float wsm[32*49];
    __shared__ float bsm[32];
    __shared__ float patch[196][32];

    int tid = threadIdx.x;
    for (int i = tid; i < 32*KK; i += 256) {
        int chl = i / KK, wi = i - chl*KK;
        wsm[chl*KK + wi] = w[(cg*32 + chl)*KK + wi];
    }
    if (tid < 32) bsm[tid] = bias[cg*32 + tid];

    int lc = tid & 31, lp = tid >> 5;
    for (int p = lp; p < 196; p += 8) {
        int py = p/14 - 3 + ty0, px = p - (p/14)*14 - 3 + tx0;
        float v = 0.f;
        if ((unsigned)py < IMG && (unsigned)px < IMG)
            v = g_qkv[((size_t)(b*N_ + 1 + py*IMG + px))*QKVC + 2*C_ + ch0 + lc];
        patch[p][lc] = v;
    }
    __syncthreads();

    float wr[KK];
#pragma unroll
    for (int i = 0; i < KK; i++) wr[i] = wsm[lc*KK + i];
    float bval = bsm[lc];

    float acc[8];
#pragma unroll
    for (int i = 0; i < 8; i++) acc[i] = 0.f;

    const int pad = KSZ/2, off = 3 - pad;
#pragma unroll
    for (int dy = 0; dy < KSZ; dy++) {
        int prow = (lp + off + dy)*14;
        float r[KSZ + 7];
#pragma unroll
        for (int x = 0; x < KSZ + 7; x++) r[x] = patch[prow + off + x][lc];
#pragma unroll
        for (int ox = 0; ox < 8; ox++)
#pragma unroll
            for (int dx = 0; dx < KSZ; dx++)
                acc[ox] += r[ox+dx]*wr[dy*KSZ+dx];
    }

    int gy = ty0 + lp;
#pragma unroll
    for (int ox = 0; ox < 8; ox++) {
        int gx = tx0 + ox;
        size_t n = (size_t)b*N_ + 1 + gy*IMG + gx;
        float q = g_qkv[n*QKVC + ch0 + lc];
        g_attn[n*C_ + ch0 + lc] += q*(acc[ox] + bval);
    }
}

// ---------------- launch ----------------------------------------------------
extern "C" void kernel_launch(void* const* d_in, const int* in_sizes, int n_in,
                              void* d_out, int out_size)
{
    const float* x       = (const float*)d_in[0];
    const float* qkv_w   = (const float*)d_in[1];
    const float* qkv_b   = (const float*)d_in[2];
    const float* proj_w  = (const float*)d_in[3];
    const float* proj_b  = (const float*)d_in[4];
    const float* conv3_w = (const float*)d_in[5];
    const float* conv3_b = (const float*)d_in[6];
    const float* conv5_w = (const float*)d_in[7];
    const float* conv5_b = (const float*)d_in[8];
    const float* conv7_w = (const float*)d_in[9];
    const float* conv7_b = (const float*)d_in[10];

    float* qkv;  cudaGetSymbolAddress((void**)&qkv,  g_qkv);
    float* attn; cudaGetSymbolAddress((void**)&attn, g_attn);

    const int GEMM_SMEM = 2 * STAGE_BYTES;                   // 48 KB
    const int FACT_SMEM = (96*96 + 96*132) * sizeof(float);  // ~85.5 KB

    static bool attr_set = false;
    if (!attr_set) {
        cudaFuncSetAttribute(k_fact, cudaFuncAttributeMaxDynamicSharedMemorySize, FACT_SMEM);
        cudaFuncSetAttribute(gemm_hmma, cudaFuncAttributeMaxDynamicSharedMemorySize, GEMM_SMEM);
        attr_set = true;
    }

    // 1) qkv = x @ qkv_w^T + b   (fp16 mma.sync m16n8k16)
    gemm_hmma<<<dim3(QKVC/256, (M_+127)/128), 256, GEMM_SMEM>>>(
        x, qkv_w, qkv_b, qkv, M_, QKVC, C_);

    // 2) softmax column stats over N
    k_stats_partial<<<dim3(B_, 3, NCHUNK), 256>>>();
    k_stats_combine<<<(B_*C_ + 255)/256, 256>>>();

    // 3) kv = k_softmax^T @ v   (split-K 16 + deterministic reduce)
    k_kv<<<dim3(B_*H_, SPLITK), 256>>>();
    k_kv_reduce<<<(B_*H_*c_*c_ + 255)/256, 256>>>();

    // 4) g_attn = scale * q @ kv
    k_fact<<<dim3(B_*H_, (N_+127)/128), 256, FACT_SMEM>>>();

    // 5) crpe: g_attn += q * dwconv(v)
    k_crpe<3><<<dim3(49, 6, B_), 256>>>(conv3_w, conv3_b, 0);
    k_crpe<5><<<dim3(49, 9, B_), 256>>>(conv5_w, conv5_b, 192);
    k_crpe<7><<<dim3(49, 9, B_), 256>>>(conv7_w, conv7_b, 480);

    // 6) out = attn @ proj_w^T + proj_b   (fp16 mma.sync m16n8k16)
    gemm_hmma<<<dim3(C_/256, (M_+127)/128), 256, GEMM_SMEM>>>(
        attn, proj_w, proj_b, (float*)d_out, M_, C_, C_);
}

// round 12
// speedup vs baseline: 2.2850x; 1.2036x over previous
#include <cuda_runtime.h>
#include <cuda_fp16.h>
#include <math.h>
#include <cstdint>

#define B_   8
#define N_   3137
#define C_   768
#define H_   8
#define c_   96
#define IMG  56
#define QKVC 2304
#define M_   (B_*N_)      // 25096

#define NCHUNK 16
#define CHUNK  197
#define SPLITK 16
#define KVCHUNK 197

// ---------------- scratch (device globals: allocation-guard compliant) ------
__device__ float  g_qkv[(size_t)M_*QKVC];         // 231 MB  q|k|v per token
__device__ float  g_attn[(size_t)M_*C_];          // 77 MB   pre-proj
__device__ __half g_xh[(size_t)M_*C_];            // 38.5 MB x in fp16
__device__ __half g_attnh[(size_t)M_*C_];         // 38.5 MB attn in fp16
__device__ __half g_qkvwh[(size_t)QKVC*C_];       // 3.5 MB
__device__ __half g_projwh[(size_t)C_*C_];        // 1.2 MB
__device__ float  g_kvpart[(size_t)SPLITK*B_*H_*c_*c_];
__device__ float  g_kv[B_*H_*c_*c_];
__device__ float  g_pmax[NCHUNK*B_*C_];
__device__ float  g_psum[NCHUNK*B_*C_];
__device__ float  g_smax[B_*C_];
__device__ float  g_sinv[B_*C_];

// ---------------- fp32 -> fp16 bulk convert ---------------------------------
__global__ __launch_bounds__(256) void f2h_kernel(
    const float* __restrict__ src, __half* __restrict__ dst, size_t n)
{
    size_t i = ((size_t)blockIdx.x * 256 + threadIdx.x) * 8;
    if (i >= n) return;
    float4 v0 = *(const float4*)(src + i);
    float4 v1 = *(const float4*)(src + i + 4);
    __half2 h0 = __floats2half2_rn(v0.x, v0.y);
    __half2 h1 = __floats2half2_rn(v0.z, v0.w);
    __half2 h2 = __floats2half2_rn(v1.x, v1.y);
    __half2 h3 = __floats2half2_rn(v1.z, v1.w);
    uint4 o;
    o.x = *(uint32_t*)&h0; o.y = *(uint32_t*)&h1;
    o.z = *(uint32_t*)&h2; o.w = *(uint32_t*)&h3;
    *(uint4*)(dst + i) = o;
}

// =====================  fp16 mma.sync GEMM: C = A @ W^T + bias  =============
// BM=128, BN=256, BK=32, 256 threads = 8 warps (2m x 4n), warp tile 64x64.
// A, W pre-converted to fp16. Row-major half tiles (64B rows) with 16B-unit
// XOR swizzle; ldmatrix.x4 fragment loads; mma.m16n8k16.f32.f16.f16.f32.

__device__ __forceinline__ uint32_t smem_u32(const void* p){
    uint32_t a;
    asm("{ .reg .u64 t; cvta.to.shared.u64 t, %1; cvt.u32.u64 %0, t; }" : "=r"(a) : "l"(p));
    return a;
}
__device__ __forceinline__ void ldsm_x4(uint32_t* r, uint32_t addr){
    asm volatile("ldmatrix.sync.aligned.m8n8.x4.shared.b16 {%0,%1,%2,%3}, [%4];"
        : "=r"(r[0]), "=r"(r[1]), "=r"(r[2]), "=r"(r[3]) : "r"(addr));
}
__device__ __forceinline__ void mma_f16(float* c, const uint32_t* a, const uint32_t* b){
    asm volatile(
        "mma.sync.aligned.m16n8k16.row.col.f32.f16.f16.f32 "
        "{%0,%1,%2,%3}, {%4,%5,%6,%7}, {%8,%9}, {%0,%1,%2,%3};"
        : "+f"(c[0]), "+f"(c[1]), "+f"(c[2]), "+f"(c[3])
        : "r"(a[0]), "r"(a[1]), "r"(a[2]), "r"(a[3]), "r"(b[0]), "r"(b[1]));
}
// swizzled byte offset inside a [rows][32 half] tile (64B rows, 16B units)
__device__ __forceinline__ uint32_t swz(int row, int unit, int lo8){
    return (uint32_t)(row * 64 + ((unit ^ ((row >> 1) & 3)) << 4) + lo8);
}

#define STAGE_BYTES 24576   // A 8KB + B 16KB per stage

__global__ __launch_bounds__(256, 1) void gemm_hmma(
    const __half* __restrict__ A, const __half* __restrict__ W,
    const float* __restrict__ bias, float* __restrict__ C,
    int M, int N, int K)
{
    extern __shared__ char smc[];
    int tid = threadIdx.x, lane = tid & 31, wid = tid >> 5;
    int warp_m = wid & 1, warp_n = wid >> 1;
    int bm = blockIdx.y * 128, bn = blockIdx.x * 256;

    float acc[4][8][4];
#pragma unroll
    for (int i = 0; i < 4; i++)
#pragma unroll
        for (int j = 0; j < 8; j++)
#pragma unroll
            for (int r = 0; r < 4; r++) acc[i][j][r] = 0.f;

    uint4 ra[2], rb[4];

    auto ldg = [&](int t){
#pragma unroll
        for (int it = 0; it < 2; it++) {
            int idx = tid + it * 256;          // 0..511
            int row = idx >> 2, u = idx & 3;   // 4 threads/row, 8 halfs each
            const __half* ap = A + (size_t)(bm + row) * K + t * 32 + u * 8;
            ra[it] = (bm + row < M) ? *(const uint4*)ap : make_uint4(0,0,0,0);
        }
#pragma unroll
        for (int it = 0; it < 4; it++) {
            int idx = tid + it * 256;          // 0..1023
            int row = idx >> 2, u = idx & 3;
            rb[it] = *(const uint4*)(W + (size_t)(bn + row) * K + t * 32 + u * 8);
        }
    };
    auto sts = [&](int t){
        char* sA = smc + (t & 1) * STAGE_BYTES;
        char* sB = sA + 8192;
#pragma unroll
        for (int it = 0; it < 2; it++) {
            int idx = tid + it * 256;
            int row = idx >> 2, u = idx & 3;
            *(uint4*)(sA + swz(row, u, 0)) = ra[it];
        }
#pragma unroll
        for (int it = 0; it < 4; it++) {
            int idx = tid + it * 256;
            int row = idx >> 2, u = idx & 3;
            *(uint4*)(sB + swz(row, u, 0)) = rb[it];
        }
    };
    auto domma = [&](int t){
        uint32_t saA = smem_u32(smc) + (t & 1) * STAGE_BYTES;
        uint32_t saB = saA + 8192;
        int bblk = lane >> 3, rr = lane & 7;
#pragma unroll
        for (int ks = 0; ks < 2; ks++) {
            uint32_t a[4][4], b[4][4];
#pragma unroll
            for (int i = 0; i < 4; i++) {
                int mtile = warp_m * 4 + i;
                int row = mtile * 16 + (bblk & 1) * 8 + rr;
                int u = ks * 2 + (bblk >> 1);
                ldsm_x4(a[i], saA + swz(row, u, 0));
            }
#pragma unroll
            for (int j2 = 0; j2 < 4; j2++) {
                int nt = warp_n * 8 + j2 * 2 + (lane >> 4);
                int kblk = (lane >> 3) & 1;
                int row = nt * 8 + rr;
                int u = ks * 2 + kblk;
                ldsm_x4(b[j2], saB + swz(row, u, 0));
            }
#pragma unroll
            for (int i = 0; i < 4; i++)
#pragma unroll
                for (int j2 = 0; j2 < 4; j2++) {
                    mma_f16(acc[i][j2*2+0], a[i], &b[j2][0]);
                    mma_f16(acc[i][j2*2+1], a[i], &b[j2][2]);
                }
        }
    };

    const int T = K / 32;
    ldg(0); sts(0);
    __syncthreads();

    for (int t = 0; t < T; t++) {
        if (t + 1 < T) ldg(t + 1);
        domma(t);
        if (t + 1 < T) sts(t + 1);
        __syncthreads();
    }

    // epilogue
    int g = lane >> 2, tg = lane & 3;
#pragma unroll
    for (int i = 0; i < 4; i++) {
        int row0 = bm + warp_m * 64 + i * 16 + g;
        int row1 = row0 + 8;
#pragma unroll
        for (int j = 0; j < 8; j++) {
            int col = bn + warp_n * 64 + j * 8 + tg * 2;
            float2 bv = *(const float2*)&bias[col];
            if (row0 < M) {
                float2 o = make_float2(acc[i][j][0] + bv.x, acc[i][j][1] + bv.y);
                *(float2*)(C + (size_t)row0 * N + col) = o;
            }
            if (row1 < M) {
                float2 o = make_float2(acc[i][j][2] + bv.x, acc[i][j][3] + bv.y);
                *(float2*)(C + (size_t)row1 * N + col) = o;
            }
        }
    }
}

// ---------------- softmax column stats over N (chunked, online) -------------
__global__ void k_stats_partial()
{
    int b = blockIdx.x, jg = blockIdx.y, ch = blockIdx.z;
    int j = jg*256 + threadIdx.x;
    int n0 = ch*CHUNK;
    int n1 = min(n0 + CHUNK, N_);
    const float* base = g_qkv + ((size_t)b*N_ + n0)*QKVC + C_ + j;
    float m = -1e30f, s = 0.f;
    for (int n = n0; n < n1; n++, base += QKVC) {
        float v = *base;
        if (v > m) { s = s*__expf(m - v) + 1.f; m = v; }
        else       { s += __expf(v - m); }
    }
    int col = b*C_ + j;
    g_pmax[ch*(B_*C_) + col] = m;
    g_psum[ch*(B_*C_) + col] = s;
}

__global__ void k_stats_combine()
{
    int col = blockIdx.x*256 + threadIdx.x;
    if (col >= B_*C_) return;
    float m = -1e30f;
#pragma unroll
    for (int ch = 0; ch < NCHUNK; ch++) m = fmaxf(m, g_pmax[ch*(B_*C_)+col]);
    float s = 0.f;
#pragma unroll
    for (int ch = 0; ch < NCHUNK; ch++) s += g_psum[ch*(B_*C_)+col]*__expf(g_pmax[ch*(B_*C_)+col]-m);
    g_smax[col] = m;
    g_sinv[col] = 1.f/s;
}

// ---------------- kv[b,h,c,d] = sum_n exp(k[n,c]-max[c]) * v[n,d] -----------
__global__ __launch_bounds__(256) void k_kv()
{
    int bh = blockIdx.x; int b = bh >> 3, h = bh & 7;
    int sk = blockIdx.y;
    int n0 = sk*KVCHUNK;
    int n1 = min(n0 + KVCHUNK, N_);

    __shared__ float Kb[2][16][96], Vb[2][16][96];
    __shared__ float smax[96];
    int tid = threadIdx.x;
    if (tid < 96) smax[tid] = g_smax[b*C_ + h*c_ + tid];
    __syncthreads();

    int tx = tid & 15, ty = tid >> 4;
    float acc[6][6];
#pragma unroll
    for (int i = 0; i < 6; i++)
#pragma unroll
        for (int j = 0; j < 6; j++) acc[i][j] = 0.f;

    int nt = (n1 - n0 + 15) >> 4;
    float4 r[3];

    auto ldg = [&](int t){
#pragma unroll
        for (int it = 0; it < 3; it++) {
            int idx = tid + it * 256;
            int rr = idx / 48, f = idx % 48;
            int n = n0 + t * 16 + rr;
            float4 v;
            if (n < n1) {
                const float* row = g_qkv + (size_t)(b*N_ + n)*QKVC;
                if (f < 24) v = *(const float4*)(row + C_ + h*c_ + f*4);
                else        v = *(const float4*)(row + 2*C_ + h*c_ + (f-24)*4);
            } else {
                float pad = (f < 24) ? -1e30f : 0.f;
                v = make_float4(pad, pad, pad, pad);
            }
            r[it] = v;
        }
    };
    auto sts = [&](int t){
        int buf = t & 1;
#pragma unroll
        for (int it = 0; it < 3; it++) {
            int idx = tid + it * 256;
            int rr = idx / 48, f = idx % 48;
            float4 v = r[it];
            if (f < 24) {
                int cc = f*4;
                float4 e;
                e.x = __expf(v.x - smax[cc+0]);
                e.y = __expf(v.y - smax[cc+1]);
                e.z = __expf(v.z - smax[cc+2]);
                e.w = __expf(v.w - smax[cc+3]);
                *(float4*)&Kb[buf][rr][cc] = e;
            } else {
                *(float4*)&Vb[buf][rr][(f-24)*4] = v;
            }
        }
    };

    ldg(0); sts(0);
    __syncthreads();

    for (int t = 0; t < nt; t++) {
        if (t + 1 < nt) ldg(t + 1);
        int buf = t & 1;
#pragma unroll
        for (int rr = 0; rr < 16; rr++) {
            float2 k0 = *(const float2*)&Kb[buf][rr][ty*6];
            float2 k1 = *(const float2*)&Kb[buf][rr][ty*6+2];
            float2 k2 = *(const float2*)&Kb[buf][rr][ty*6+4];
            float2 v0 = *(const float2*)&Vb[buf][rr][tx*6];
            float2 v1 = *(const float2*)&Vb[buf][rr][tx*6+2];
            float2 v2 = *(const float2*)&Vb[buf][rr][tx*6+4];
            float ka[6] = {k0.x,k0.y,k1.x,k1.y,k2.x,k2.y};
            float vb[6] = {v0.x,v0.y,v1.x,v1.y,v2.x,v2.y};
#pragma unroll
            for (int i = 0; i < 6; i++)
#pragma unroll
                for (int j = 0; j < 6; j++) acc[i][j] += ka[i]*vb[j];
        }
        if (t + 1 < nt) sts(t + 1);
        __syncthreads();
    }

    float* out = g_kvpart + ((size_t)sk*(B_*H_) + bh)*(c_*c_);
#pragma unroll
    for (int i = 0; i < 6; i++)
#pragma unroll
        for (int j = 0; j < 6; j++)
            out[(ty*6+i)*96 + tx*6 + j] = acc[i][j];
}

__global__ void k_kv_reduce()
{
    int i = blockIdx.x*256 + threadIdx.x;
    if (i >= B_*H_*c_*c_) return;
    int bh = i / (c_*c_);
    int rem = i - bh*(c_*c_);
    int cc = rem / c_;
    int b = bh >> 3, h = bh & 7;
    float s = 0.f;
#pragma unroll
    for (int sk = 0; sk < SPLITK; sk++)
        s += g_kvpart[((size_t)sk*(B_*H_) + bh)*(c_*c_) + rem];
    g_kv[i] = s * g_sinv[b*C_ + h*c_ + cc];
}

// ---------------- factor_att: g_attn = scale * q @ kv -----------------------
__global__ __launch_bounds__(256) void k_fact()
{
    extern __shared__ float smf[];
    float* kvs = smf;             // [96][96]
    float* qst = smf + 96*96;     // [96][132]

    int bh = blockIdx.x; int b = bh >> 3, h = bh & 7;
    int n0 = blockIdx.y * 128;
    int tid = threadIdx.x;

    for (int i = tid; i < 96*96; i += 256) kvs[i] = g_kv[(size_t)bh*(c_*c_) + i];
    for (int i = tid; i < 128*96; i += 256) {
        int rr = i / 96, j = i - rr*96;
        int n = n0 + rr;
        float q = 0.f;
        if (n < N_) q = g_qkv[((size_t)(b*N_+n))*QKVC + h*c_ + j];
        qst[j*132 + rr] = q;
    }
    __syncthreads();

    int tx = tid & 15, ty = tid >> 4;
    float acc[8][6];
#pragma unroll
    for (int i = 0; i < 8; i++)
#pragma unroll
        for (int j = 0; j < 6; j++) acc[i][j] = 0.f;

#pragma unroll 2
    for (int k = 0; k < 96; k++) {
        float4 q0 = *(const float4*)&qst[k*132 + ty*8];
        float4 q1 = *(const float4*)&qst[k*132 + ty*8 + 4];
        float2 b0 = *(const float2*)&kvs[k*96 + tx*6];
        float2 b1 = *(const float2*)&kvs[k*96 + tx*6 + 2];
        float2 b2 = *(const float2*)&kvs[k*96 + tx*6 + 4];
        float qa[8] = {q0.x,q0.y,q0.z,q0.w,q1.x,q1.y,q1.z,q1.w};
        float bb[6] = {b0.x,b0.y,b1.x,b1.y,b2.x,b2.y};
#pragma unroll
        for (int i = 0; i < 8; i++)
#pragma unroll
            for (int j = 0; j < 6; j++) acc[i][j] += qa[i]*bb[j];
    }

    const float scale = 0.10206207261596577f;
#pragma unroll
    for (int i = 0; i < 8; i++) {
        int n = n0 + ty*8 + i;
        if (n < N_) {
            float* o = g_attn + ((size_t)(b*N_+n))*C_ + h*c_ + tx*6;
            *(float2*)(o)   = make_float2(scale*acc[i][0], scale*acc[i][1]);
            *(float2*)(o+2) = make_float2(scale*acc[i][2], scale*acc[i][3]);
            *(float2*)(o+4) = make_float2(scale*acc[i][4], scale*acc[i][5]);
        }
    }
}

// ---------------- crpe: g_attn += q * (dwconv(v) + bias) --------------------
template <int KSZ>
__global__ __launch_bounds__(256) void k_crpe(const float* __restrict__ w,
                                              const float* __restrict__ bias,
                                              int ch_base)
{
    const int KK = KSZ*KSZ;
    int tile = blockIdx.x;
    int cg   = blockIdx.y;
    int b    = blockIdx.z;
    int ch0  = ch_base + cg*32;
    int ty0  = (tile/7)*8, tx0 = (tile%7)*8;

    __shared__ float wsm[32*49];
    __shared__ float bsm[32];
    __shared__ float patch[196][32];

    int tid = threadIdx.x;
    for (int i = tid; i < 32*KK; i += 256) {
        int chl = i / KK, wi = i - chl*KK;
        wsm[chl*KK + wi] = w[(cg*32 + chl)*KK + wi];
    }
    if (tid < 32) bsm[tid] = bias[cg*32 + tid];

    int lc = tid & 31, lp = tid >> 5;
    for (int p = lp; p < 196; p += 8) {
        int py = p/14 - 3 + ty0, px = p - (p/14)*14 - 3 + tx0;
        float v = 0.f;
        if ((unsigned)py < IMG && (unsigned)px < IMG)
            v = g_qkv[((size_t)(b*N_ + 1 + py*IMG + px))*QKVC + 2*C_ + ch0 + lc];
        patch[p][lc] = v;
    }
    __syncthreads();

    float wr[KK];
#pragma unroll
    for (int i = 0; i < KK; i++) wr[i] = wsm[lc*KK + i];
    float bval = bsm[lc];

    float acc[8];
#pragma unroll
    for (int i = 0; i < 8; i++) acc[i] = 0.f;

    const int pad = KSZ/2, off = 3 - pad;
#pragma unroll
    for (int dy = 0; dy < KSZ; dy++) {
        int prow = (lp + off + dy)*14;
        float r[KSZ + 7];
#pragma unroll
        for (int x = 0; x < KSZ + 7; x++) r[x] = patch[prow + off + x][lc];
#pragma unroll
        for (int ox = 0; ox < 8; ox++)
#pragma unroll
            for (int dx = 0; dx < KSZ; dx++)
                acc[ox] += r[ox+dx]*wr[dy*KSZ+dx];
    }

    int gy = ty0 + lp;
#pragma unroll
    for (int ox = 0; ox < 8; ox++) {
        int gx = tx0 + ox;
        size_t n = (size_t)b*N_ + 1 + gy*IMG + gx;
        float q = g_qkv[n*QKVC + ch0 + lc];
        g_attn[n*C_ + ch0 + lc] += q*(acc[ox] + bval);
    }
}

// ---------------- launch ----------------------------------------------------
extern "C" void kernel_launch(void* const* d_in, const int* in_sizes, int n_in,
                              void* d_out, int out_size)
{
    const float* x       = (const float*)d_in[0];
    const float* qkv_w   = (const float*)d_in[1];
    const float* qkv_b   = (const float*)d_in[2];
    const float* proj_w  = (const float*)d_in[3];
    const float* proj_b  = (const float*)d_in[4];
    const float* conv3_w = (const float*)d_in[5];
    const float* conv3_b = (const float*)d_in[6];
    const float* conv5_w = (const float*)d_in[7];
    const float* conv5_b = (const float*)d_in[8];
    const float* conv7_w = (const float*)d_in[9];
    const float* conv7_b = (const float*)d_in[10];

    float*  qkv;   cudaGetSymbolAddress((void**)&qkv,   g_qkv);
    float*  attn;  cudaGetSymbolAddress((void**)&attn,  g_attn);
    __half* xh;    cudaGetSymbolAddress((void**)&xh,    g_xh);
    __half* attnh; cudaGetSymbolAddress((void**)&attnh, g_attnh);
    __half* qwh;   cudaGetSymbolAddress((void**)&qwh,   g_qkvwh);
    __half* pwh;   cudaGetSymbolAddress((void**)&pwh,   g_projwh);

    const int GEMM_SMEM = 2 * STAGE_BYTES;                   // 48 KB
    const int FACT_SMEM = (96*96 + 96*132) * sizeof(float);  // ~85.5 KB

    static bool attr_set = false;
    if (!attr_set) {
        cudaFuncSetAttribute(k_fact, cudaFuncAttributeMaxDynamicSharedMemorySize, FACT_SMEM);
        cudaFuncSetAttribute(gemm_hmma, cudaFuncAttributeMaxDynamicSharedMemorySize, GEMM_SMEM);
        attr_set = true;
    }

    // 0) fp16 copies of GEMM inputs
    f2h_kernel<<<(size_t)(M_*(size_t)C_)/8/256 + 1, 256>>>(x, xh, (size_t)M_*C_);
    f2h_kernel<<<(size_t)(QKVC*(size_t)C_)/8/256 + 1, 256>>>(qkv_w, qwh, (size_t)QKVC*C_);
    f2h_kernel<<<(size_t)(C_*(size_t)C_)/8/256 + 1, 256>>>(proj_w, pwh, (size_t)C_*C_);

    // 1) qkv = x @ qkv_w^T + b   (fp16 mma.sync m16n8k16)
    gemm_hmma<<<dim3(QKVC/256, (M_+127)/128), 256, GEMM_SMEM>>>(
        xh, qwh, qkv_b, qkv, M_, QKVC, C_);

    // 2) softmax column stats over N
    k_stats_partial<<<dim3(B_, 3, NCHUNK), 256>>>();
    k_stats_combine<<<(B_*C_ + 255)/256, 256>>>();

    // 3) kv = k_softmax^T @ v   (split-K 16 + deterministic reduce)
    k_kv<<<dim3(B_*H_, SPLITK), 256>>>();
    k_kv_reduce<<<(B_*H_*c_*c_ + 255)/256, 256>>>();

    // 4) g_attn = scale * q @ kv
    k_fact<<<dim3(B_*H_, (N_+127)/128), 256, FACT_SMEM>>>();

    // 5) crpe: g_attn += q * dwconv(v)
    k_crpe<3><<<dim3(49, 6, B_), 256>>>(conv3_w, conv3_b, 0);
    k_crpe<5><<<dim3(49, 9, B_), 256>>>(conv5_w, conv5_b, 192);
    k_crpe<7><<<dim3(49, 9, B_), 256>>>(conv7_w, conv7_b, 480);

    // 5b) attn -> fp16
    f2h_kernel<<<(size_t)(M_*(size_t)C_)/8/256 + 1, 256>>>(attn, attnh, (size_t)M_*C_);

    // 6) out = attn @ proj_w^T + proj_b   (fp16 mma.sync m16n8k16)
    gemm_hmma<<<dim3(C_/256, (M_+127)/128), 256, GEMM_SMEM>>>(
        attnh, pwh, proj_b, (float*)d_out, M_, C_, C_);
}

// round 13
// speedup vs baseline: 2.3336x; 1.0213x over previous
#include <cuda_runtime.h>
#include <cuda_fp16.h>
#include <math.h>
#include <cstdint>

#define B_   8
#define N_   3137
#define C_   768
#define H_   8
#define c_   96
#define IMG  56
#define QKVC 2304
#define M_   (B_*N_)      // 25096

#define NCHUNK 16
#define CHUNK  197
#define SPLITK 16
#define KVCHUNK 197

// ---------------- scratch (device globals: allocation-guard compliant) ------
__device__ float  g_qkv[(size_t)M_*QKVC];         // 231 MB  q|k|v per token
__device__ float  g_attn[(size_t)M_*C_];          // 77 MB   pre-proj
__device__ __half g_xh[(size_t)M_*C_];            // 38.5 MB x in fp16
__device__ __half g_attnh[(size_t)M_*C_];         // 38.5 MB attn in fp16
__device__ __half g_qkvwh[(size_t)QKVC*C_];       // 3.5 MB
__device__ __half g_projwh[(size_t)C_*C_];        // 1.2 MB
__device__ float  g_kvpart[(size_t)SPLITK*B_*H_*c_*c_];
__device__ float  g_kv[B_*H_*c_*c_];
__device__ float  g_pmax[NCHUNK*B_*C_];
__device__ float  g_psum[NCHUNK*B_*C_];
__device__ float  g_smax[B_*C_];
__device__ float  g_sinv[B_*C_];

// ---------------- fp32 -> fp16 bulk convert ---------------------------------
__global__ __launch_bounds__(256) void f2h_kernel(
    const float* __restrict__ src, __half* __restrict__ dst, size_t n)
{
    size_t i = ((size_t)blockIdx.x * 256 + threadIdx.x) * 8;
    if (i >= n) return;
    float4 v0 = *(const float4*)(src + i);
    float4 v1 = *(const float4*)(src + i + 4);
    __half2 h0 = __floats2half2_rn(v0.x, v0.y);
    __half2 h1 = __floats2half2_rn(v0.z, v0.w);
    __half2 h2 = __floats2half2_rn(v1.x, v1.y);
    __half2 h3 = __floats2half2_rn(v1.z, v1.w);
    uint4 o;
    o.x = *(uint32_t*)&h0; o.y = *(uint32_t*)&h1;
    o.z = *(uint32_t*)&h2; o.w = *(uint32_t*)&h3;
    *(uint4*)(dst + i) = o;
}

// =====================  fp16 mma.sync GEMM: C = A @ W^T + bias  =============
// BM=128, BN=256, BK=32, 256 threads = 8 warps (2m x 4n), warp tile 64x64.
// A, W pre-converted to fp16. Row-major half tiles (64B rows) with 16B-unit
// XOR swizzle; ldmatrix.x4 fragment loads; mma.m16n8k16.f32.f16.f16.f32.

__device__ __forceinline__ uint32_t smem_u32(const void* p){
    uint32_t a;
    asm("{ .reg .u64 t; cvta.to.shared.u64 t, %1; cvt.u32.u64 %0, t; }" : "=r"(a) : "l"(p));
    return a;
}
__device__ __forceinline__ void ldsm_x4(uint32_t* r, uint32_t addr){
    asm volatile("ldmatrix.sync.aligned.m8n8.x4.shared.b16 {%0,%1,%2,%3}, [%4];"
        : "=r"(r[0]), "=r"(r[1]), "=r"(r[2]), "=r"(r[3]) : "r"(addr));
}
__device__ __forceinline__ void mma_f16(float* c, const uint32_t* a, const uint32_t* b){
    asm volatile(
        "mma.sync.aligned.m16n8k16.row.col.f32.f16.f16.f32 "
        "{%0,%1,%2,%3}, {%4,%5,%6,%7}, {%8,%9}, {%0,%1,%2,%3};"
        : "+f"(c[0]), "+f"(c[1]), "+f"(c[2]), "+f"(c[3])
        : "r"(a[0]), "r"(a[1]), "r"(a[2]), "r"(a[3]), "r"(b[0]), "r"(b[1]));
}
// swizzled byte offset inside a [rows][32 half] tile (64B rows, 16B units)
__device__ __forceinline__ uint32_t swz(int row, int unit, int lo8){
    return (uint32_t)(row * 64 + ((unit ^ ((row >> 1) & 3)) << 4) + lo8);
}

#define STAGE_BYTES 24576   // A 8KB + B 16KB per stage

__global__ __launch_bounds__(256, 1) void gemm_hmma(
    const __half* __restrict__ A, const __half* __restrict__ W,
    const float* __restrict__ bias, float* __restrict__ C,
    int M, int N, int K)
{
    extern __shared__ char smc[];
    int tid = threadIdx.x, lane = tid & 31, wid = tid >> 5;
    int warp_m = wid & 1, warp_n = wid >> 1;
    int bm = blockIdx.y * 128, bn = blockIdx.x * 256;

    float acc[4][8][4];
#pragma unroll
    for (int i = 0; i < 4; i++)
#pragma unroll
        for (int j = 0; j < 8; j++)
#pragma unroll
            for (int r = 0; r < 4; r++) acc[i][j][r] = 0.f;

    uint4 ra[2], rb[4];

    auto ldg = [&](int t){
#pragma unroll
        for (int it = 0; it < 2; it++) {
            int idx = tid + it * 256;          // 0..511
            int row = idx >> 2, u = idx & 3;   // 4 threads/row, 8 halfs each
            const __half* ap = A + (size_t)(bm + row) * K + t * 32 + u * 8;
            ra[it] = (bm + row < M) ? *(const uint4*)ap : make_uint4(0,0,0,0);
        }
#pragma unroll
        for (int it = 0; it < 4; it++) {
            int idx = tid + it * 256;          // 0..1023
            int row = idx >> 2, u = idx & 3;
            rb[it] = *(const uint4*)(W + (size_t)(bn + row) * K + t * 32 + u * 8);
        }
    };
    auto sts = [&](int t){
        char* sA = smc + (t & 1) * STAGE_BYTES;
        char* sB = sA + 8192;
#pragma unroll
        for (int it = 0; it < 2; it++) {
            int idx = tid + it * 256;
            int row = idx >> 2, u = idx & 3;
            *(uint4*)(sA + swz(row, u, 0)) = ra[it];
        }
#pragma unroll
        for (int it = 0; it < 4; it++) {
            int idx = tid + it * 256;
            int row = idx >> 2, u = idx & 3;
            *(uint4*)(sB + swz(row, u, 0)) = rb[it];
        }
    };
    auto domma = [&](int t){
        uint32_t saA = smem_u32(smc) + (t & 1) * STAGE_BYTES;
        uint32_t saB = saA + 8192;
        int bblk = lane >> 3, rr = lane & 7;
#pragma unroll
        for (int ks = 0; ks < 2; ks++) {
            uint32_t a[4][4], b[4][4];
#pragma unroll
            for (int i = 0; i < 4; i++) {
                int mtile = warp_m * 4 + i;
                int row = mtile * 16 + (bblk & 1) * 8 + rr;
                int u = ks * 2 + (bblk >> 1);
                ldsm_x4(a[i], saA + swz(row, u, 0));
            }
#pragma unroll
            for (int j2 = 0; j2 < 4; j2++) {
                int nt = warp_n * 8 + j2 * 2 + (lane >> 4);
                int kblk = (lane >> 3) & 1;
                int row = nt * 8 + rr;
                int u = ks * 2 + kblk;
                ldsm_x4(b[j2], saB + swz(row, u, 0));
            }
#pragma unroll
            for (int i = 0; i < 4; i++)
#pragma unroll
                for (int j2 = 0; j2 < 4; j2++) {
                    mma_f16(acc[i][j2*2+0], a[i], &b[j2][0]);
                    mma_f16(acc[i][j2*2+1], a[i], &b[j2][2]);
                }
        }
    };

    const int T = K / 32;
    ldg(0); sts(0);
    __syncthreads();

    for (int t = 0; t < T; t++) {
        if (t + 1 < T) ldg(t + 1);
        domma(t);
        if (t + 1 < T) sts(t + 1);
        __syncthreads();
    }

    // epilogue
    int g = lane >> 2, tg = lane & 3;
#pragma unroll
    for (int i = 0; i < 4; i++) {
        int row0 = bm + warp_m * 64 + i * 16 + g;
        int row1 = row0 + 8;
#pragma unroll
        for (int j = 0; j < 8; j++) {
            int col = bn + warp_n * 64 + j * 8 + tg * 2;
            float2 bv = *(const float2*)&bias[col];
            if (row0 < M) {
                float2 o = make_float2(acc[i][j][0] + bv.x, acc[i][j][1] + bv.y);
                *(float2*)(C + (size_t)row0 * N + col) = o;
            }
            if (row1 < M) {
                float2 o = make_float2(acc[i][j][2] + bv.x, acc[i][j][3] + bv.y);
                *(float2*)(C + (size_t)row1 * N + col) = o;
            }
        }
    }
}

// ---------------- softmax column stats over N (chunked, online) -------------
__global__ void k_stats_partial()
{
    int b = blockIdx.x, jg = blockIdx.y, ch = blockIdx.z;
    int j = jg*256 + threadIdx.x;
    int n0 = ch*CHUNK;
    int n1 = min(n0 + CHUNK, N_);
    const float* base = g_qkv + ((size_t)b*N_ + n0)*QKVC + C_ + j;
    float m = -1e30f, s = 0.f;
    for (int n = n0; n < n1; n++, base += QKVC) {
        float v = *base;
        if (v > m) { s = s*__expf(m - v) + 1.f; m = v; }
        else       { s += __expf(v - m); }
    }
    int col = b*C_ + j;
    g_pmax[ch*(B_*C_) + col] = m;
    g_psum[ch*(B_*C_) + col] = s;
}

__global__ void k_stats_combine()
{
    int col = blockIdx.x*256 + threadIdx.x;
    if (col >= B_*C_) return;
    float m = -1e30f;
#pragma unroll
    for (int ch = 0; ch < NCHUNK; ch++) m = fmaxf(m, g_pmax[ch*(B_*C_)+col]);
    float s = 0.f;
#pragma unroll
    for (int ch = 0; ch < NCHUNK; ch++) s += g_psum[ch*(B_*C_)+col]*__expf(g_pmax[ch*(B_*C_)+col]-m);
    g_smax[col] = m;
    g_sinv[col] = 1.f/s;
}

// ---------------- kv[b,h,c,d] = sum_n exp(k[n,c]-max[c]) * v[n,d] -----------
__global__ __launch_bounds__(256) void k_kv()
{
    int bh = blockIdx.x; int b = bh >> 3, h = bh & 7;
    int sk = blockIdx.y;
    int n0 = sk*KVCHUNK;
    int n1 = min(n0 + KVCHUNK, N_);

    __shared__ float Kb[2][16][96], Vb[2][16][96];
    __shared__ float smax[96];
    int tid = threadIdx.x;
    if (tid < 96) smax[tid] = g_smax[b*C_ + h*c_ + tid];
    __syncthreads();

    int tx = tid & 15, ty = tid >> 4;
    float acc[6][6];
#pragma unroll
    for (int i = 0; i < 6; i++)
#pragma unroll
        for (int j = 0; j < 6; j++) acc[i][j] = 0.f;

    int nt = (n1 - n0 + 15) >> 4;
    float4 r[3];

    auto ldg = [&](int t){
#pragma unroll
        for (int it = 0; it < 3; it++) {
            int idx = tid + it * 256;
            int rr = idx / 48, f = idx % 48;
            int n = n0 + t * 16 + rr;
            float4 v;
            if (n < n1) {
                const float* row = g_qkv + (size_t)(b*N_ + n)*QKVC;
                if (f < 24) v = *(const float4*)(row + C_ + h*c_ + f*4);
                else        v = *(const float4*)(row + 2*C_ + h*c_ + (f-24)*4);
            } else {
                float pad = (f < 24) ? -1e30f : 0.f;
                v = make_float4(pad, pad, pad, pad);
            }
            r[it] = v;
        }
    };
    auto sts = [&](int t){
        int buf = t & 1;
#pragma unroll
        for (int it = 0; it < 3; it++) {
            int idx = tid + it * 256;
            int rr = idx / 48, f = idx % 48;
            float4 v = r[it];
            if (f < 24) {
                int cc = f*4;
                float4 e;
                e.x = __expf(v.x - smax[cc+0]);
                e.y = __expf(v.y - smax[cc+1]);
                e.z = __expf(v.z - smax[cc+2]);
                e.w = __expf(v.w - smax[cc+3]);
                *(float4*)&Kb[buf][rr][cc] = e;
            } else {
                *(float4*)&Vb[buf][rr][(f-24)*4] = v;
            }
        }
    };

    ldg(0); sts(0);
    __syncthreads();

    for (int t = 0; t < nt; t++) {
        if (t + 1 < nt) ldg(t + 1);
        int buf = t & 1;
#pragma unroll
        for (int rr = 0; rr < 16; rr++) {
            float2 k0 = *(const float2*)&Kb[buf][rr][ty*6];
            float2 k1 = *(const float2*)&Kb[buf][rr][ty*6+2];
            float2 k2 = *(const float2*)&Kb[buf][rr][ty*6+4];
            float2 v0 = *(const float2*)&Vb[buf][rr][tx*6];
            float2 v1 = *(const float2*)&Vb[buf][rr][tx*6+2];
            float2 v2 = *(const float2*)&Vb[buf][rr][tx*6+4];
            float ka[6] = {k0.x,k0.y,k1.x,k1.y,k2.x,k2.y};
            float vb[6] = {v0.x,v0.y,v1.x,v1.y,v2.x,v2.y};
#pragma unroll
            for (int i = 0; i < 6; i++)
#pragma unroll
                for (int j = 0; j < 6; j++) acc[i][j] += ka[i]*vb[j];
        }
        if (t + 1 < nt) sts(t + 1);
        __syncthreads();
    }

    float* out = g_kvpart + ((size_t)sk*(B_*H_) + bh)*(c_*c_);
#pragma unroll
    for (int i = 0; i < 6; i++)
#pragma unroll
        for (int j = 0; j < 6; j++)
            out[(ty*6+i)*96 + tx*6 + j] = acc[i][j];
}

__global__ void k_kv_reduce()
{
    int i = blockIdx.x*256 + threadIdx.x;
    if (i >= B_*H_*c_*c_) return;
    int bh = i / (c_*c_);
    int rem = i - bh*(c_*c_);
    int cc = rem / c_;
    int b = bh >> 3, h = bh & 7;
    float s = 0.f;
#pragma unroll
    for (int sk = 0; sk < SPLITK; sk++)
        s += g_kvpart[((size_t)sk*(B_*H_) + bh)*(c_*c_) + rem];
    g_kv[i] = s * g_sinv[b*C_ + h*c_ + cc];
}

// ---------------- factor_att: g_attn = scale * q @ kv -----------------------
__global__ __launch_bounds__(256) void k_fact()
{
    extern __shared__ float smf[];
    float* kvs = smf;             // [96][96]
    float* qst = smf + 96*96;     // [96][132]

    int bh = blockIdx.x; int b = bh >> 3, h = bh & 7;
    int n0 = blockIdx.y * 128;
    int tid = threadIdx.x;

    for (int i = tid; i < 96*96; i += 256) kvs[i] = g_kv[(size_t)bh*(c_*c_) + i];
    for (int i = tid; i < 128*96; i += 256) {
        int rr = i / 96, j = i - rr*96;
        int n = n0 + rr;
        float q = 0.f;
        if (n < N_) q = g_qkv[((size_t)(b*N_+n))*QKVC + h*c_ + j];
        qst[j*132 + rr] = q;
    }
    __syncthreads();

    int tx = tid & 15, ty = tid >> 4;
    float acc[8][6];
#pragma unroll
    for (int i = 0; i < 8; i++)
#pragma unroll
        for (int j = 0; j < 6; j++) acc[i][j] = 0.f;

#pragma unroll 2
    for (int k = 0; k < 96; k++) {
        float4 q0 = *(const float4*)&qst[k*132 + ty*8];
        float4 q1 = *(const float4*)&qst[k*132 + ty*8 + 4];
        float2 b0 = *(const float2*)&kvs[k*96 + tx*6];
        float2 b1 = *(const float2*)&kvs[k*96 + tx*6 + 2];
        float2 b2 = *(const float2*)&kvs[k*96 + tx*6 + 4];
        float qa[8] = {q0.x,q0.y,q0.z,q0.w,q1.x,q1.y,q1.z,q1.w};
        float bb[6] = {b0.x,b0.y,b1.x,b1.y,b2.x,b2.y};
#pragma unroll
        for (int i = 0; i < 8; i++)
#pragma unroll
            for (int j = 0; j < 6; j++) acc[i][j] += qa[i]*bb[j];
    }

    const float scale = 0.10206207261596577f;
#pragma unroll
    for (int i = 0; i < 8; i++) {
        int n = n0 + ty*8 + i;
        if (n < N_) {
            float* o = g_attn + ((size_t)(b*N_+n))*C_ + h*c_ + tx*6;
            *(float2*)(o)   = make_float2(scale*acc[i][0], scale*acc[i][1]);
            *(float2*)(o+2) = make_float2(scale*acc[i][2], scale*acc[i][3]);
            *(float2*)(o+4) = make_float2(scale*acc[i][4], scale*acc[i][5]);
        }
    }
}

// ---------------- crpe: g_attn += q * (dwconv(v) + bias) --------------------
template <int KSZ>
__global__ __launch_bounds__(256) void k_crpe(const float* __restrict__ w,
                                              const float* __restrict__ bias,
                                              int ch_base)
{
    const int KK = KSZ*KSZ;
    int tile = blockIdx.x;
    int cg   = blockIdx.y;
    int b    = blockIdx.z;
    int ch0  = ch_base + cg*32;
    int ty0  = (tile/7)*8, tx0 = (tile%7)*8;

    __shared__ float wsm[32*49];
    __shared__ float bsm[32];
    __shared__ float patch[196][32];

    int tid = threadIdx.x;
    for (int i = tid; i < 32*KK; i += 256) {
        int chl = i / KK, wi = i - chl*KK;
        wsm[chl*KK + wi] = w[(cg*32 + chl)*KK + wi];
    }
    if (tid < 32) bsm[tid] = bias[cg*32 + tid];

    int lc = tid & 31, lp = tid >> 5;
    for (int p = lp; p < 196; p += 8) {
        int py = p/14 - 3 + ty0, px = p - (p/14)*14 - 3 + tx0;
        float v = 0.f;
        if ((unsigned)py < IMG && (unsigned)px < IMG)
            v = g_qkv[((size_t)(b*N_ + 1 + py*IMG + px))*QKVC + 2*C_ + ch0 + lc];
        patch[p][lc] = v;
    }
    __syncthreads();

    float wr[KK];
#pragma unroll
    for (int i = 0; i < KK; i++) wr[i] = wsm[lc*KK + i];
    float bval = bsm[lc];

    float acc[8];
#pragma unroll
    for (int i = 0; i < 8; i++) acc[i] = 0.f;

    const int pad = KSZ/2, off = 3 - pad;
#pragma unroll
    for (int dy = 0; dy < KSZ; dy++) {
        int prow = (lp + off + dy)*14;
        float r[KSZ + 7];
#pragma unroll
        for (int x = 0; x < KSZ + 7; x++) r[x] = patch[prow + off + x][lc];
#pragma unroll
        for (int ox = 0; ox < 8; ox++)
#pragma unroll
            for (int dx = 0; dx < KSZ; dx++)
                acc[ox] += r[ox+dx]*wr[dy*KSZ+dx];
    }

    int gy = ty0 + lp;
#pragma unroll
    for (int ox = 0; ox < 8; ox++) {
        int gx = tx0 + ox;
        size_t n = (size_t)b*N_ + 1 + gy*IMG + gx;
        float q = g_qkv[n*QKVC + ch0 + lc];
        g_attn[n*C_ + ch0 + lc] += q*(acc[ox] + bval);
    }
}

// ---------------- launch ----------------------------------------------------
extern "C" void kernel_launch(void* const* d_in, const int* in_sizes, int n_in,
                              void* d_out, int out_size)
{
    const float* x       = (const float*)d_in[0];
    const float* qkv_w   = (const float*)d_in[1];
    const float* qkv_b   = (const float*)d_in[2];
    const float* proj_w  = (const float*)d_in[3];
    const float* proj_b  = (const float*)d_in[4];
    const float* conv3_w = (const float*)d_in[5];
    const float* conv3_b = (const float*)d_in[6];
    const float* conv5_w = (const float*)d_in[7];
    const float* conv5_b = (const float*)d_in[8];
    const float* conv7_w = (const float*)d_in[9];
    const float* conv7_b = (const float*)d_in[10];

    float*  qkv;   cudaGetSymbolAddress((void**)&qkv,   g_qkv);
    float*  attn;  cudaGetSymbolAddress((void**)&attn,  g_attn);
    __half* xh;    cudaGetSymbolAddress((void**)&xh,    g_xh);
    __half* attnh; cudaGetSymbolAddress((void**)&attnh, g_attnh);
    __half* qwh;   cudaGetSymbolAddress((void**)&qwh,   g_qkvwh);
    __half* pwh;   cudaGetSymbolAddress((void**)&pwh,   g_projwh);

    const int GEMM_SMEM = 2 * STAGE_BYTES;                   // 48 KB
    const int FACT_SMEM = (96*96 + 96*132) * sizeof(float);  // ~85.5 KB

    static bool attr_set = false;
    if (!attr_set) {
        cudaFuncSetAttribute(k_fact, cudaFuncAttributeMaxDynamicSharedMemorySize, FACT_SMEM);
        cudaFuncSetAttribute(gemm_hmma, cudaFuncAttributeMaxDynamicSharedMemorySize, GEMM_SMEM);
        attr_set = true;
    }

    // 0) fp16 copies of GEMM inputs
    f2h_kernel<<<(size_t)(M_*(size_t)C_)/8/256 + 1, 256>>>(x, xh, (size_t)M_*C_);
    f2h_kernel<<<(size_t)(QKVC*(size_t)C_)/8/256 + 1, 256>>>(qkv_w, qwh, (size_t)QKVC*C_);
    f2h_kernel<<<(size_t)(C_*(size_t)C_)/8/256 + 1, 256>>>(proj_w, pwh, (size_t)C_*C_);

    // 1) qkv = x @ qkv_w^T + b   (fp16 mma.sync m16n8k16)
    gemm_hmma<<<dim3(QKVC/256, (M_+127)/128), 256, GEMM_SMEM>>>(
        xh, qwh, qkv_b, qkv, M_, QKVC, C_);

    // 2) softmax column stats over N
    k_stats_partial<<<dim3(B_, 3, NCHUNK), 256>>>();
    k_stats_combine<<<(B_*C_ + 255)/256, 256>>>();

    // 3) kv = k_softmax^T @ v   (split-K 16 + deterministic reduce)
    k_kv<<<dim3(B_*H_, SPLITK), 256>>>();
    k_kv_reduce<<<(B_*H_*c_*c_ + 255)/256, 256>>>();

    // 4) g_attn = scale * q @ kv
    k_fact<<<dim3(B_*H_, (N_+127)/128), 256, FACT_SMEM>>>();

    // 5) crpe: g_attn += q * dwconv(v)
    k_crpe<3><<<dim3(49, 6, B_), 256>>>(conv3_w, conv3_b, 0);
    k_crpe<5><<<dim3(49, 9, B_), 256>>>(conv5_w, conv5_b, 192);
    k_crpe<7><<<dim3(49, 9, B_), 256>>>(conv7_w, conv7_b, 480);

    // 5b) attn -> fp16
    f2h_kernel<<<(size_t)(M_*(size_t)C_)/8/256 + 1, 256>>>(attn, attnh, (size_t)M_*C_);

    // 6) out = attn @ proj_w^T + proj_b   (fp16 mma.sync m16n8k16)
    gemm_hmma<<<dim3(C_/256, (M_+127)/128), 256, GEMM_SMEM>>>(
        attnh, pwh, proj_b, (float*)d_out, M_, C_, C_);
}

// round 16
// speedup vs baseline: 2.3660x; 1.0139x over previous
#include <cuda_runtime.h>
#include <cuda_fp16.h>
#include <math.h>
#include <cstdint>

#define B_   8
#define N_   3137
#define C_   768
#define H_   8
#define c_   96
#define IMG  56
#define QKVC 2304
#define M_   (B_*N_)      // 25096

#define NCHUNK 16
#define CHUNK  197
#define SPLITK 16
#define KVCHUNK 197

// ---------------- scratch (device globals: allocation-guard compliant) ------
__device__ float  g_qkv[(size_t)M_*QKVC];         // 231 MB  q|k|v per token
__device__ __half g_xh[(size_t)M_*C_];            // 38.5 MB x in fp16
__device__ __half g_attnh[(size_t)M_*C_];         // 38.5 MB attn in fp16
__device__ __half g_qkvwh[(size_t)QKVC*C_];       // 3.5 MB
__device__ __half g_projwh[(size_t)C_*C_];        // 1.2 MB
__device__ float  g_kvpart[(size_t)SPLITK*B_*H_*c_*c_];
__device__ float  g_kv[B_*H_*c_*c_];
__device__ float  g_pmax[NCHUNK*B_*C_];
__device__ float  g_psum[NCHUNK*B_*C_];
__device__ float  g_smax[B_*C_];
__device__ float  g_sinv[B_*C_];

// ---------------- fp32 -> fp16 bulk convert ---------------------------------
__global__ __launch_bounds__(256) void f2h_kernel(
    const float* __restrict__ src, __half* __restrict__ dst, size_t n)
{
    size_t i = ((size_t)blockIdx.x * 256 + threadIdx.x) * 8;
    if (i >= n) return;
    float4 v0 = *(const float4*)(src + i);
    float4 v1 = *(const float4*)(src + i + 4);
    __half2 h0 = __floats2half2_rn(v0.x, v0.y);
    __half2 h1 = __floats2half2_rn(v0.z, v0.w);
    __half2 h2 = __floats2half2_rn(v1.x, v1.y);
    __half2 h3 = __floats2half2_rn(v1.z, v1.w);
    uint4 o;
    o.x = *(uint32_t*)&h0; o.y = *(uint32_t*)&h1;
    o.z = *(uint32_t*)&h2; o.w = *(uint32_t*)&h3;
    *(uint4*)(dst + i) = o;
}

// =====================  fp16 mma.sync GEMM: C = A @ W^T + bias  =============
// BM=128, BN=256, BK=32, 256 threads = 8 warps (2m x 4n), warp tile 64x64.
// cp.async 3-stage pipeline; swizzled half tiles; ldmatrix.x4; m16n8k16.

__device__ __forceinline__ uint32_t smem_u32(const void* p){
    uint32_t a;
    asm("{ .reg .u64 t; cvta.to.shared.u64 t, %1; cvt.u32.u64 %0, t; }" : "=r"(a) : "l"(p));
    return a;
}
__device__ __forceinline__ void cp_async16(uint32_t dst, const void* src, int szbytes){
    asm volatile("cp.async.cg.shared.global [%0], [%1], 16, %2;"
        :: "r"(dst), "l"(src), "r"(szbytes) : "memory");
}
__device__ __forceinline__ void cp_commit(){
    asm volatile("cp.async.commit_group;" ::: "memory");
}
template<int N>
__device__ __forceinline__ void cp_wait(){
    asm volatile("cp.async.wait_group %0;" :: "n"(N) : "memory");
}
__device__ __forceinline__ void ldsm_x4(uint32_t* r, uint32_t addr){
    asm volatile("ldmatrix.sync.aligned.m8n8.x4.shared.b16 {%0,%1,%2,%3}, [%4];"
        : "=r"(r[0]), "=r"(r[1]), "=r"(r[2]), "=r"(r[3]) : "r"(addr));
}
__device__ __forceinline__ void mma_f16(float* c, const uint32_t* a, const uint32_t* b){
    asm volatile(
        "mma.sync.aligned.m16n8k16.row.col.f32.f16.f16.f32 "
        "{%0,%1,%2,%3}, {%4,%5,%6,%7}, {%8,%9}, {%0,%1,%2,%3};"
        : "+f"(c[0]), "+f"(c[1]), "+f"(c[2]), "+f"(c[3])
        : "r"(a[0]), "r"(a[1]), "r"(a[2]), "r"(a[3]), "r"(b[0]), "r"(b[1]));
}
// swizzled byte offset inside a [rows][32 half] tile (64B rows, 16B units)
__device__ __forceinline__ uint32_t swz(int row, int unit, int lo8){
    return (uint32_t)(row * 64 + ((unit ^ ((row >> 1) & 3)) << 4) + lo8);
}

#define STAGE_BYTES 24576   // A 8KB + B 16KB per stage
#define NSTAGE 3

__global__ __launch_bounds__(256, 1) void gemm_hmma(
    const __half* __restrict__ A, const __half* __restrict__ W,
    const float* __restrict__ bias, float* __restrict__ C,
    int M, int N, int K)
{
    extern __shared__ char smc[];
    uint32_t smbase = smem_u32(smc);
    int tid = threadIdx.x, lane = tid & 31, wid = tid >> 5;
    int warp_m = wid & 1, warp_n = wid >> 1;
    int bm = blockIdx.y * 128, bn = blockIdx.x * 256;

    float acc[4][8][4];
#pragma unroll
    for (int i = 0; i < 4; i++)
#pragma unroll
        for (int j = 0; j < 8; j++)
#pragma unroll
            for (int r = 0; r < 4; r++) acc[i][j][r] = 0.f;

    auto stage_cp = [&](int t){
        uint32_t sA = smbase + (t % NSTAGE) * STAGE_BYTES;
        uint32_t sB = sA + 8192;
#pragma unroll
        for (int it = 0; it < 2; it++) {
            int idx = tid + it * 256;          // 0..511
            int row = idx >> 2, u = idx & 3;
            int gr = bm + row;
            int sz = (gr < M) ? 16 : 0;
            const __half* src = A + (size_t)(gr < M ? gr : M - 1) * K + t * 32 + u * 8;
            cp_async16(sA + swz(row, u, 0), src, sz);
        }
#pragma unroll
        for (int it = 0; it < 4; it++) {
            int idx = tid + it * 256;          // 0..1023
            int row = idx >> 2, u = idx & 3;
            cp_async16(sB + swz(row, u, 0),
                       W + (size_t)(bn + row) * K + t * 32 + u * 8, 16);
        }
        cp_commit();
    };
    auto domma = [&](int t){
        uint32_t saA = smbase + (t % NSTAGE) * STAGE_BYTES;
        uint32_t saB = saA + 8192;
        int bblk = lane >> 3, rr = lane & 7;
#pragma unroll
        for (int ks = 0; ks < 2; ks++) {
            uint32_t a[4][4], b[4][4];
#pragma unroll
            for (int i = 0; i < 4; i++) {
                int mtile = warp_m * 4 + i;
                int row = mtile * 16 + (bblk & 1) * 8 + rr;
                int u = ks * 2 + (bblk >> 1);
                ldsm_x4(a[i], saA + swz(row, u, 0));
            }
#pragma unroll
            for (int j2 = 0; j2 < 4; j2++) {
                int nt = warp_n * 8 + j2 * 2 + (lane >> 4);
                int kblk = (lane >> 3) & 1;
                int row = nt * 8 + rr;
                int u = ks * 2 + kblk;
                ldsm_x4(b[j2], saB + swz(row, u, 0));
            }
#pragma unroll
            for (int i = 0; i < 4; i++)
#pragma unroll
                for (int j2 = 0; j2 < 4; j2++) {
                    mma_f16(acc[i][j2*2+0], a[i], &b[j2][0]);
                    mma_f16(acc[i][j2*2+1], a[i], &b[j2][2]);
                }
        }
    };

    const int T = K / 32;
    stage_cp(0);
    stage_cp(1);
    cp_wait<1>();
    __syncthreads();

    for (int t = 0; t < T; t++) {
        if (t + 2 < T) stage_cp(t + 2);
        domma(t);
        if (t + 1 < T) {
            if (t + 2 < T) cp_wait<1>();
            else           cp_wait<0>();
            __syncthreads();
        }
    }

    // epilogue
    int g = lane >> 2, tg = lane & 3;
#pragma unroll
    for (int i = 0; i < 4; i++) {
        int row0 = bm + warp_m * 64 + i * 16 + g;
        int row1 = row0 + 8;
#pragma unroll
        for (int j = 0; j < 8; j++) {
            int col = bn + warp_n * 64 + j * 8 + tg * 2;
            float2 bv = *(const float2*)&bias[col];
            if (row0 < M) {
                float2 o = make_float2(acc[i][j][0] + bv.x, acc[i][j][1] + bv.y);
                *(float2*)(C + (size_t)row0 * N + col) = o;
            }
            if (row1 < M) {
                float2 o = make_float2(acc[i][j][2] + bv.x, acc[i][j][3] + bv.y);
                *(float2*)(C + (size_t)row1 * N + col) = o;
            }
        }
    }
}

// ---------------- softmax column stats over N (chunked, online) -------------
__global__ void k_stats_partial()
{
    int b = blockIdx.x, jg = blockIdx.y, ch = blockIdx.z;
    int j = jg*256 + threadIdx.x;
    int n0 = ch*CHUNK;
    int n1 = min(n0 + CHUNK, N_);
    const float* base = g_qkv + ((size_t)b*N_ + n0)*QKVC + C_ + j;
    float m = -1e30f, s = 0.f;
    for (int n = n0; n < n1; n++, base += QKVC) {
        float v = *base;
        if (v > m) { s = s*__expf(m - v) + 1.f; m = v; }
        else       { s += __expf(v - m); }
    }
    int col = b*C_ + j;
    g_pmax[ch*(B_*C_) + col] = m;
    g_psum[ch*(B_*C_) + col] = s;
}

__global__ void k_stats_combine()
{
    int col = blockIdx.x*256 + threadIdx.x;
    if (col >= B_*C_) return;
    float m = -1e30f;
#pragma unroll
    for (int ch = 0; ch < NCHUNK; ch++) m = fmaxf(m, g_pmax[ch*(B_*C_)+col]);
    float s = 0.f;
#pragma unroll
    for (int ch = 0; ch < NCHUNK; ch++) s += g_psum[ch*(B_*C_)+col]*__expf(g_pmax[ch*(B_*C_)+col]-m);
    g_smax[col] = m;
    g_sinv[col] = 1.f/s;
}

// ---------------- kv[b,h,c,d] = sum_n exp(k[n,c]-max[c]) * v[n,d] -----------
__global__ __launch_bounds__(256) void k_kv()
{
    int bh = blockIdx.x; int b = bh >> 3, h = bh & 7;
    int sk = blockIdx.y;
    int n0 = sk*KVCHUNK;
    int n1 = min(n0 + KVCHUNK, N_);

    __shared__ float Kb[2][16][96], Vb[2][16][96];
    __shared__ float smax[96];
    int tid = threadIdx.x;
    if (tid < 96) smax[tid] = g_smax[b*C_ + h*c_ + tid];
    __syncthreads();

    int tx = tid & 15, ty = tid >> 4;
    float acc[6][6];
#pragma unroll
    for (int i = 0; i < 6; i++)
#pragma unroll
        for (int j = 0; j < 6; j++) acc[i][j] = 0.f;

    int nt = (n1 - n0 + 15) >> 4;
    float4 r[3];

    auto ldg = [&](int t){
#pragma unroll
        for (int it = 0; it < 3; it++) {
            int idx = tid + it * 256;
            int rr = idx / 48, f = idx % 48;
            int n = n0 + t * 16 + rr;
            float4 v;
            if (n < n1) {
                const float* row = g_qkv + (size_t)(b*N_ + n)*QKVC;
                if (f < 24) v = *(const float4*)(row + C_ + h*c_ + f*4);
                else        v = *(const float4*)(row + 2*C_ + h*c_ + (f-24)*4);
            } else {
                float pad = (f < 24) ? -1e30f : 0.f;
                v = make_float4(pad, pad, pad, pad);
            }
            r[it] = v;
        }
    };
    auto sts = [&](int t){
        int buf = t & 1;
#pragma unroll
        for (int it = 0; it < 3; it++) {
            int idx = tid + it * 256;
            int rr = idx / 48, f = idx % 48;
            float4 v = r[it];
            if (f < 24) {
                int cc = f*4;
                float4 e;
                e.x = __expf(v.x - smax[cc+0]);
                e.y = __expf(v.y - smax[cc+1]);
                e.z = __expf(v.z - smax[cc+2]);
                e.w = __expf(v.w - smax[cc+3]);
                *(float4*)&Kb[buf][rr][cc] = e;
            } else {
                *(float4*)&Vb[buf][rr][(f-24)*4] = v;
            }
        }
    };

    ldg(0); sts(0);
    __syncthreads();

    for (int t = 0; t < nt; t++) {
        if (t + 1 < nt) ldg(t + 1);
        int buf = t & 1;
#pragma unroll
        for (int rr = 0; rr < 16; rr++) {
            float2 k0 = *(const float2*)&Kb[buf][rr][ty*6];
            float2 k1 = *(const float2*)&Kb[buf][rr][ty*6+2];
            float2 k2 = *(const float2*)&Kb[buf][rr][ty*6+4];
            float2 v0 = *(const float2*)&Vb[buf][rr][tx*6];
            float2 v1 = *(const float2*)&Vb[buf][rr][tx*6+2];
            float2 v2 = *(const float2*)&Vb[buf][rr][tx*6+4];
            float ka[6] = {k0.x,k0.y,k1.x,k1.y,k2.x,k2.y};
            float vb[6] = {v0.x,v0.y,v1.x,v1.y,v2.x,v2.y};
#pragma unroll
            for (int i = 0; i < 6; i++)
#pragma unroll
                for (int j = 0; j < 6; j++) acc[i][j] += ka[i]*vb[j];
        }
        if (t + 1 < nt) sts(t + 1);
        __syncthreads();
    }

    float* out = g_kvpart + ((size_t)sk*(B_*H_) + bh)*(c_*c_);
#pragma unroll
    for (int i = 0; i < 6; i++)
#pragma unroll
        for (int j = 0; j < 6; j++)
            out[(ty*6+i)*96 + tx*6 + j] = acc[i][j];
}

__global__ void k_kv_reduce()
{
    int i = blockIdx.x*256 + threadIdx.x;
    if (i >= B_*H_*c_*c_) return;
    int bh = i / (c_*c_);
    int rem = i - bh*(c_*c_);
    int cc = rem / c_;
    int b = bh >> 3, h = bh & 7;
    float s = 0.f;
#pragma unroll
    for (int sk = 0; sk < SPLITK; sk++)
        s += g_kvpart[((size_t)sk*(B_*H_) + bh)*(c_*c_) + rem];
    g_kv[i] = s * g_sinv[b*C_ + h*c_ + cc];
}

// ---------------- factor_att: g_attnh = half(scale * q @ kv) ----------------
__global__ __launch_bounds__(256) void k_fact()
{
    extern __shared__ float smf[];
    float* kvs = smf;             // [96][96]
    float* qst = smf + 96*96;     // [96][132]

    int bh = blockIdx.x; int b = bh >> 3, h = bh & 7;
    int n0 = blockIdx.y * 128;
    int tid = threadIdx.x;

    for (int i = tid; i < 96*96; i += 256) kvs[i] = g_kv[(size_t)bh*(c_*c_) + i];
    for (int i = tid; i < 128*96; i += 256) {
        int rr = i / 96, j = i - rr*96;
        int n = n0 + rr;
        float q = 0.f;
        if (n < N_) q = g_qkv[((size_t)(b*N_+n))*QKVC + h*c_ + j];
        qst[j*132 + rr] = q;
    }
    __syncthreads();

    int tx = tid & 15, ty = tid >> 4;
    float acc[8][6];
#pragma unroll
    for (int i = 0; i < 8; i++)
#pragma unroll
        for (int j = 0; j < 6; j++) acc[i][j] = 0.f;

#pragma unroll 2
    for (int k = 0; k < 96; k++) {
        float4 q0 = *(const float4*)&qst[k*132 + ty*8];
        float4 q1 = *(const float4*)&qst[k*132 + ty*8 + 4];
        float2 b0 = *(const float2*)&kvs[k*96 + tx*6];
        float2 b1 = *(const float2*)&kvs[k*96 + tx*6 + 2];
        float2 b2 = *(const float2*)&kvs[k*96 + tx*6 + 4];
        float qa[8] = {q0.x,q0.y,q0.z,q0.w,q1.x,q1.y,q1.z,q1.w};
        float bb[6] = {b0.x,b0.y,b1.x,b1.y,b2.x,b2.y};
#pragma unroll
        for (int i = 0; i < 8; i++)
#pragma unroll
            for (int j = 0; j < 6; j++) acc[i][j] += qa[i]*bb[j];
    }

    const float scale = 0.10206207261596577f;
#pragma unroll
    for (int i = 0; i < 8; i++) {
        int n = n0 + ty*8 + i;
        if (n < N_) {
            __half* o = g_attnh + ((size_t)(b*N_+n))*C_ + h*c_ + tx*6;
            __half2 h0 = __floats2half2_rn(scale*acc[i][0], scale*acc[i][1]);
            __half2 h1 = __floats2half2_rn(scale*acc[i][2], scale*acc[i][3]);
            __half2 h2 = __floats2half2_rn(scale*acc[i][4], scale*acc[i][5]);
            *(__half2*)(o)   = h0;
            *(__half2*)(o+2) = h1;
            *(__half2*)(o+4) = h2;
        }
    }
}

// ---------------- crpe: g_attnh += half(q * (dwconv(v) + bias)) -------------
template <int KSZ>
__global__ __launch_bounds__(256) void k_crpe(const float* __restrict__ w,
                                              const float* __restrict__ bias,
                                              int ch_base)
{
    const int KK = KSZ*KSZ;
    int tile = blockIdx.x;
    int cg   = blockIdx.y;
    int b    = blockIdx.z;
    int ch0  = ch_base + cg*32;
    int ty0  = (tile/7)*8, tx0 = (tile%7)*8;

    __shared__ float wsm[32*49];
    __shared__ float bsm[32];
    __shared__ float patch[196][32];

    int tid = threadIdx.x;
    for (int i = tid; i < 32*KK; i += 256) {
        int chl = i / KK, wi = i - chl*KK;
        wsm[chl*KK + wi] = w[(cg*32 + chl)*KK + wi];
    }
    if (tid < 32) bsm[tid] = bias[cg*32 + tid];

    int lc = tid & 31, lp = tid >> 5;
    for (int p = lp; p < 196; p += 8) {
        int py = p/14 - 3 + ty0, px = p - (p/14)*14 - 3 + tx0;
        float v = 0.f;
        if ((unsigned)py < IMG && (unsigned)px < IMG)
            v = g_qkv[((size_t)(b*N_ + 1 + py*IMG + px))*QKVC + 2*C_ + ch0 + lc];
        patch[p][lc] = v;
    }
    __syncthreads();

    float wr[KK];
#pragma unroll
    for (int i = 0; i < KK; i++) wr[i] = wsm[lc*KK + i];
    float bval = bsm[lc];

    float acc[8];
#pragma unroll
    for (int i = 0; i < 8; i++) acc[i] = 0.f;

    const int pad = KSZ/2, off = 3 - pad;
#pragma unroll
    for (int dy = 0; dy < KSZ; dy++) {
        int prow = (lp + off + dy)*14;
        float r[KSZ + 7];
#pragma unroll
        for (int x = 0; x < KSZ + 7; x++) r[x] = patch[prow + off + x][lc];
#pragma unroll
        for (int ox = 0; ox < 8; ox++)
#pragma unroll
            for (int dx = 0; dx < KSZ; dx++)
                acc[ox] += r[ox+dx]*wr[dy*KSZ+dx];
    }

    int gy = ty0 + lp;
#pragma unroll
    for (int ox = 0; ox < 8; ox++) {
        int gx = tx0 + ox;
        size_t n = (size_t)b*N_ + 1 + gy*IMG + gx;
        float q = g_qkv[n*QKVC + ch0 + lc];
        __half* a = g_attnh + n*C_ + ch0 + lc;
        float cur = __half2float(*a);
        *a = __float2half(cur + q*(acc[ox] + bval));
    }
}

// ---------------- launch ----------------------------------------------------
extern "C" void kernel_launch(void* const* d_in, const int* in_sizes, int n_in,
                              void* d_out, int out_size)
{
    const float* x       = (const float*)d_in[0];
    const float* qkv_w   = (const float*)d_in[1];
    const float* qkv_b   = (const float*)d_in[2];
    const float* proj_w  = (const float*)d_in[3];
    const float* proj_b  = (const float*)d_in[4];
    const float* conv3_w = (const float*)d_in[5];
    const float* conv3_b = (const float*)d_in[6];
    const float* conv5_w = (const float*)d_in[7];
    const float* conv5_b = (const float*)d_in[8];
    const float* conv7_w = (const float*)d_in[9];
    const float* conv7_b = (const float*)d_in[10];

    float*  qkv;   cudaGetSymbolAddress((void**)&qkv,   g_qkv);
    __half* xh;    cudaGetSymbolAddress((void**)&xh,    g_xh);
    __half* attnh; cudaGetSymbolAddress((void**)&attnh, g_attnh);
    __half* qwh;   cudaGetSymbolAddress((void**)&qwh,   g_qkvwh);
    __half* pwh;   cudaGetSymbolAddress((void**)&pwh,   g_projwh);

    const int GEMM_SMEM = NSTAGE * STAGE_BYTES;              // 72 KB
    const int FACT_SMEM = (96*96 + 96*132) * sizeof(float);  // ~85.5 KB

    static bool attr_set = false;
    if (!attr_set) {
        cudaFuncSetAttribute(k_fact, cudaFuncAttributeMaxDynamicSharedMemorySize, FACT_SMEM);
        cudaFuncSetAttribute(gemm_hmma, cudaFuncAttributeMaxDynamicSharedMemorySize, GEMM_SMEM);
        attr_set = true;
    }

    // 0) fp16 copies of GEMM inputs
    f2h_kernel<<<(size_t)(M_*(size_t)C_)/8/256 + 1, 256>>>(x, xh, (size_t)M_*C_);
    f2h_kernel<<<(size_t)(QKVC*(size_t)C_)/8/256 + 1, 256>>>(qkv_w, qwh, (size_t)QKVC*C_);
    f2h_kernel<<<(size_t)(C_*(size_t)C_)/8/256 + 1, 256>>>(proj_w, pwh, (size_t)C_*C_);

    // 1) qkv = x @ qkv_w^T + b   (fp16 mma.sync + cp.async)
    gemm_hmma<<<dim3(QKVC/256, (M_+127)/128), 256, GEMM_SMEM>>>(
        xh, qwh, qkv_b, qkv, M_, QKVC, C_);

    // 2) softmax column stats over N
    k_stats_partial<<<dim3(B_, 3, NCHUNK), 256>>>();
    k_stats_combine<<<(B_*C_ + 255)/256, 256>>>();

    // 3) kv = k_softmax^T @ v   (split-K 16 + deterministic reduce)
    k_kv<<<dim3(B_*H_, SPLITK), 256>>>();
    k_kv_reduce<<<(B_*H_*c_*c_ + 255)/256, 256>>>();

    // 4) g_attnh = half(scale * q @ kv)
    k_fact<<<dim3(B_*H_, (N_+127)/128), 256, FACT_SMEM>>>();

    // 5) crpe: g_attnh += half(q * dwconv(v))
    k_crpe<3><<<dim3(49, 6, B_), 256>>>(conv3_w, conv3_b, 0);
    k_crpe<5><<<dim3(49, 9, B_), 256>>>(conv5_w, conv5_b, 192);
    k_crpe<7><<<dim3(49, 9, B_), 256>>>(conv7_w, conv7_b, 480);

    // 6) out = attn @ proj_w^T + proj_b   (fp16 mma.sync + cp.async)
    gemm_hmma<<<dim3(C_/256, (M_+127)/128), 256, GEMM_SMEM>>>(
        attnh, pwh, proj_b, (float*)d_out, M_, C_, C_);
}

// round 17
// speedup vs baseline: 2.4836x; 1.0497x over previous
#include <cuda_runtime.h>
#include <cuda_fp16.h>
#include <math.h>
#include <cstdint>

#define B_   8
#define N_   3137
#define C_   768
#define H_   8
#define c_   96
#define IMG  56
#define QKVC 2304
#define M_   (B_*N_)      // 25096

#define NCHUNK 16
#define CHUNK  197
#define SPLITK 16
#define KVCHUNK 197
#define KVPS  (96*96 + 96)   // kv block + column sums

// ---------------- scratch (device globals: allocation-guard compliant) ------
__device__ float  g_qkv[(size_t)M_*QKVC];         // 231 MB  q|k|v per token
__device__ __half g_xh[(size_t)M_*C_];            // 38.5 MB x in fp16
__device__ __half g_attnh[(size_t)M_*C_];         // 38.5 MB attn in fp16
__device__ __half g_qkvwh[(size_t)QKVC*C_];       // 3.5 MB
__device__ __half g_projwh[(size_t)C_*C_];        // 1.2 MB
__device__ float  g_kvpart[(size_t)SPLITK*B_*H_*KVPS];
__device__ float  g_kv[B_*H_*c_*c_];
__device__ float  g_pmax[NCHUNK*B_*C_];
__device__ float  g_smax[B_*C_];
__device__ float  g_sinv2[B_*H_*c_];

// ---------------- fast exp: poly 2^f, FMA pipe only (x <= 0 here) -----------
__device__ __forceinline__ float fast_exp(float x){
    float t = x * 1.4426950408889634f;
    t = fmaxf(t, -126.0f);
    float n = floorf(t);
    float f = t - n;
    float p = 1.5252734e-4f;                 // ln2^6/720
    p = fmaf(p, f, 1.3333558e-3f);           // ln2^5/120
    p = fmaf(p, f, 9.6181291e-3f);
    p = fmaf(p, f, 5.5504109e-2f);
    p = fmaf(p, f, 2.4022651e-1f);
    p = fmaf(p, f, 6.9314718e-1f);
    p = fmaf(p, f, 1.0f);
    float sc = __int_as_float(((int)n + 127) << 23);
    return p * sc;
}

// ---------------- fp32 -> fp16 bulk convert ---------------------------------
__global__ __launch_bounds__(256) void f2h_kernel(
    const float* __restrict__ src, __half* __restrict__ dst, size_t n)
{
    size_t i = ((size_t)blockIdx.x * 256 + threadIdx.x) * 8;
    if (i >= n) return;
    float4 v0 = *(const float4*)(src + i);
    float4 v1 = *(const float4*)(src + i + 4);
    __half2 h0 = __floats2half2_rn(v0.x, v0.y);
    __half2 h1 = __floats2half2_rn(v0.z, v0.w);
    __half2 h2 = __floats2half2_rn(v1.x, v1.y);
    __half2 h3 = __floats2half2_rn(v1.z, v1.w);
    uint4 o;
    o.x = *(uint32_t*)&h0; o.y = *(uint32_t*)&h1;
    o.z = *(uint32_t*)&h2; o.w = *(uint32_t*)&h3;
    *(uint4*)(dst + i) = o;
}

// =====================  fp16 mma.sync GEMM: C = A @ W^T + bias  =============
// BM=128, BN=256, BK=64 (2x32 sub-chunks), 3-stage cp.async (144KB smem).

__device__ __forceinline__ uint32_t smem_u32(const void* p){
    uint32_t a;
    asm("{ .reg .u64 t; cvta.to.shared.u64 t, %1; cvt.u32.u64 %0, t; }" : "=r"(a) : "l"(p));
    return a;
}
__device__ __forceinline__ void cp_async16(uint32_t dst, const void* src, int szbytes){
    asm volatile("cp.async.cg.shared.global [%0], [%1], 16, %2;"
        :: "r"(dst), "l"(src), "r"(szbytes) : "memory");
}
__device__ __forceinline__ void cp_commit(){
    asm volatile("cp.async.commit_group;" ::: "memory");
}
template<int N>
__device__ __forceinline__ void cp_wait(){
    asm volatile("cp.async.wait_group %0;" :: "n"(N) : "memory");
}
__device__ __forceinline__ void ldsm_x4(uint32_t* r, uint32_t addr){
    asm volatile("ldmatrix.sync.aligned.m8n8.x4.shared.b16 {%0,%1,%2,%3}, [%4];"
        : "=r"(r[0]), "=r"(r[1]), "=r"(r[2]), "=r"(r[3]) : "r"(addr));
}
__device__ __forceinline__ void mma_f16(float* c, const uint32_t* a, const uint32_t* b){
    asm volatile(
        "mma.sync.aligned.m16n8k16.row.col.f32.f16.f16.f32 "
        "{%0,%1,%2,%3}, {%4,%5,%6,%7}, {%8,%9}, {%0,%1,%2,%3};"
        : "+f"(c[0]), "+f"(c[1]), "+f"(c[2]), "+f"(c[3])
        : "r"(a[0]), "r"(a[1]), "r"(a[2]), "r"(a[3]), "r"(b[0]), "r"(b[1]));
}
// swizzled byte offset inside a [rows][32 half] sub-tile (64B rows, 16B units)
__device__ __forceinline__ uint32_t swz(int row, int unit, int lo8){
    return (uint32_t)(row * 64 + ((unit ^ ((row >> 1) & 3)) << 4) + lo8);
}

#define SUB_BYTES   24576        // A 8KB + B 16KB per 32-k sub-chunk
#define STAGE_BYTES (2*SUB_BYTES)  // BK=64
#define NSTAGE 3                 // 144 KB

__global__ __launch_bounds__(256, 1) void gemm_hmma(
    const __half* __restrict__ A, const __half* __restrict__ W,
    const float* __restrict__ bias, float* __restrict__ C,
    int M, int N, int K)
{
    extern __shared__ char smc[];
    uint32_t smbase = smem_u32(smc);
    int tid = threadIdx.x, lane = tid & 31, wid = tid >> 5;
    int warp_m = wid & 1, warp_n = wid >> 1;
    int bm = blockIdx.y * 128, bn = blockIdx.x * 256;

    float acc[4][8][4];
#pragma unroll
    for (int i = 0; i < 4; i++)
#pragma unroll
        for (int j = 0; j < 8; j++)
#pragma unroll
            for (int r = 0; r < 4; r++) acc[i][j][r] = 0.f;

    auto stage_cp = [&](int t){   // t = 64-k chunk index
#pragma unroll
        for (int sub = 0; sub < 2; sub++) {
            uint32_t base = smbase + (t % NSTAGE) * STAGE_BYTES + sub * SUB_BYTES;
            uint32_t sA = base, sB = base + 8192;
            int k0 = t * 64 + sub * 32;
#pragma unroll
            for (int it = 0; it < 2; it++) {
                int idx = tid + it * 256;
                int row = idx >> 2, u = idx & 3;
                int gr = bm + row;
                int sz = (gr < M) ? 16 : 0;
                const __half* src = A + (size_t)(gr < M ? gr : M - 1) * K + k0 + u * 8;
                cp_async16(sA + swz(row, u, 0), src, sz);
            }
#pragma unroll
            for (int it = 0; it < 4; it++) {
                int idx = tid + it * 256;
                int row = idx >> 2, u = idx & 3;
                cp_async16(sB + swz(row, u, 0),
                           W + (size_t)(bn + row) * K + k0 + u * 8, 16);
            }
        }
        cp_commit();
    };
    auto domma = [&](int t){
        int bblk = lane >> 3, rr = lane & 7;
#pragma unroll
        for (int sub = 0; sub < 2; sub++) {
            uint32_t saA = smbase + (t % NSTAGE) * STAGE_BYTES + sub * SUB_BYTES;
            uint32_t saB = saA + 8192;
#pragma unroll
            for (int ks = 0; ks < 2; ks++) {
                uint32_t a[4][4], b[4][4];
#pragma unroll
                for (int i = 0; i < 4; i++) {
                    int mtile = warp_m * 4 + i;
                    int row = mtile * 16 + (bblk & 1) * 8 + rr;
                    int u = ks * 2 + (bblk >> 1);
                    ldsm_x4(a[i], saA + swz(row, u, 0));
                }
#pragma unroll
                for (int j2 = 0; j2 < 4; j2++) {
                    int nt = warp_n * 8 + j2 * 2 + (lane >> 4);
                    int kblk = (lane >> 3) & 1;
                    int row = nt * 8 + rr;
                    int u = ks * 2 + kblk;
                    ldsm_x4(b[j2], saB + swz(row, u, 0));
                }
#pragma unroll
                for (int i = 0; i < 4; i++)
#pragma unroll
                    for (int j2 = 0; j2 < 4; j2++) {
                        mma_f16(acc[i][j2*2+0], a[i], &b[j2][0]);
                        mma_f16(acc[i][j2*2+1], a[i], &b[j2][2]);
                    }
            }
        }
    };

    const int T2 = K / 64;   // 12
    stage_cp(0);
    stage_cp(1);
    cp_wait<1>();
    __syncthreads();

    for (int t = 0; t < T2; t++) {
        if (t + 2 < T2) stage_cp(t + 2);
        domma(t);
        if (t + 1 < T2) {
            if (t + 2 < T2) cp_wait<1>();
            else            cp_wait<0>();
            __syncthreads();
        }
    }

    // epilogue
    int g = lane >> 2, tg = lane & 3;
#pragma unroll
    for (int i = 0; i < 4; i++) {
        int row0 = bm + warp_m * 64 + i * 16 + g;
        int row1 = row0 + 8;
#pragma unroll
        for (int j = 0; j < 8; j++) {
            int col = bn + warp_n * 64 + j * 8 + tg * 2;
            float2 bv = *(const float2*)&bias[col];
            if (row0 < M) {
                float2 o = make_float2(acc[i][j][0] + bv.x, acc[i][j][1] + bv.y);
                *(float2*)(C + (size_t)row0 * N + col) = o;
            }
            if (row1 < M) {
                float2 o = make_float2(acc[i][j][2] + bv.x, acc[i][j][3] + bv.y);
                *(float2*)(C + (size_t)row1 * N + col) = o;
            }
        }
    }
}

// ---------------- softmax column MAX over N (no sums; sums fold into kv) ----
__global__ void k_stats_partial()
{
    int b = blockIdx.x, jg = blockIdx.y, ch = blockIdx.z;
    int j = jg*256 + threadIdx.x;
    int n0 = ch*CHUNK;
    int n1 = min(n0 + CHUNK, N_);
    const float* base = g_qkv + ((size_t)b*N_ + n0)*QKVC + C_ + j;
    float m = -1e30f;
    for (int n = n0; n < n1; n++, base += QKVC) m = fmaxf(m, *base);
    g_pmax[ch*(B_*C_) + b*C_ + j] = m;
}

__global__ void k_stats_combine()
{
    int col = blockIdx.x*256 + threadIdx.x;
    if (col >= B_*C_) return;
    float m = -1e30f;
#pragma unroll
    for (int ch = 0; ch < NCHUNK; ch++) m = fmaxf(m, g_pmax[ch*(B_*C_)+col]);
    g_smax[col] = m;
}

// ---------------- kv[b,h,c,d] = sum_n exp(k[n,c]-max[c]) * v[n,d] -----------
// Also accumulates per-column sums S[c] (softmax denominator) into kvpart.
__global__ __launch_bounds__(256) void k_kv()
{
    int bh = blockIdx.x; int b = bh >> 3, h = bh & 7;
    int sk = blockIdx.y;
    int n0 = sk*KVCHUNK;
    int n1 = min(n0 + KVCHUNK, N_);

    __shared__ float Kb[2][16][96], Vb[2][16][96];
    __shared__ float smax[96];
    int tid = threadIdx.x;
    if (tid < 96) smax[tid] = g_smax[b*C_ + h*c_ + tid];
    __syncthreads();

    int tx = tid & 15, ty = tid >> 4;
    float acc[6][6];
#pragma unroll
    for (int i = 0; i < 6; i++)
#pragma unroll
        for (int j = 0; j < 6; j++) acc[i][j] = 0.f;
    float csum = 0.f;

    int nt = (n1 - n0 + 15) >> 4;
    float4 r[3];

    auto ldg = [&](int t){
#pragma unroll
        for (int it = 0; it < 3; it++) {
            int idx = tid + it * 256;
            int rr = idx / 48, f = idx % 48;
            int n = n0 + t * 16 + rr;
            float4 v;
            if (n < n1) {
                const float* row = g_qkv + (size_t)(b*N_ + n)*QKVC;
                if (f < 24) v = *(const float4*)(row + C_ + h*c_ + f*4);
                else        v = *(const float4*)(row + 2*C_ + h*c_ + (f-24)*4);
            } else {
                float pad = (f < 24) ? -1e30f : 0.f;
                v = make_float4(pad, pad, pad, pad);
            }
            r[it] = v;
        }
    };
    auto sts = [&](int t){
        int buf = t & 1;
#pragma unroll
        for (int it = 0; it < 3; it++) {
            int idx = tid + it * 256;
            int rr = idx / 48, f = idx % 48;
            float4 v = r[it];
            if (f < 24) {
                int cc = f*4;
                float4 e;
                e.x = fast_exp(v.x - smax[cc+0]);
                e.y = fast_exp(v.y - smax[cc+1]);
                e.z = fast_exp(v.z - smax[cc+2]);
                e.w = fast_exp(v.w - smax[cc+3]);
                *(float4*)&Kb[buf][rr][cc] = e;
            } else {
                *(float4*)&Vb[buf][rr][(f-24)*4] = v;
            }
        }
    };

    ldg(0); sts(0);
    __syncthreads();

    for (int t = 0; t < nt; t++) {
        if (t + 1 < nt) ldg(t + 1);
        int buf = t & 1;
#pragma unroll
        for (int rr = 0; rr < 16; rr++) {
            float2 k0 = *(const float2*)&Kb[buf][rr][ty*6];
            float2 k1 = *(const float2*)&Kb[buf][rr][ty*6+2];
            float2 k2 = *(const float2*)&Kb[buf][rr][ty*6+4];
            float2 v0 = *(const float2*)&Vb[buf][rr][tx*6];
            float2 v1 = *(const float2*)&Vb[buf][rr][tx*6+2];
            float2 v2 = *(const float2*)&Vb[buf][rr][tx*6+4];
            float ka[6] = {k0.x,k0.y,k1.x,k1.y,k2.x,k2.y};
            float vb[6] = {v0.x,v0.y,v1.x,v1.y,v2.x,v2.y};
#pragma unroll
            for (int i = 0; i < 6; i++)
#pragma unroll
                for (int j = 0; j < 6; j++) acc[i][j] += ka[i]*vb[j];
        }
        // fold softmax denominator: column sums of this K tile
        if (tid < 96) {
            float cs = 0.f;
#pragma unroll
            for (int rr = 0; rr < 16; rr++) cs += Kb[buf][rr][tid];
            csum += cs;
        }
        if (t + 1 < nt) sts(t + 1);
        __syncthreads();
    }

    float* out = g_kvpart + ((size_t)sk*(B_*H_) + bh)*KVPS;
#pragma unroll
    for (int i = 0; i < 6; i++)
#pragma unroll
        for (int j = 0; j < 6; j++)
            out[(ty*6+i)*96 + tx*6 + j] = acc[i][j];
    if (tid < 96) out[96*96 + tid] = csum;
}

__global__ void k_sinv()
{
    int i = blockIdx.x*256 + threadIdx.x;
    if (i >= B_*H_*c_) return;
    int bh = i / c_, cc = i - bh*c_;
    float s = 0.f;
#pragma unroll
    for (int sk = 0; sk < SPLITK; sk++)
        s += g_kvpart[((size_t)sk*(B_*H_) + bh)*KVPS + 96*96 + cc];
    g_sinv2[i] = 1.f / s;
}

__global__ void k_kv_reduce()
{
    int i = blockIdx.x*256 + threadIdx.x;
    if (i >= B_*H_*c_*c_) return;
    int bh = i / (c_*c_);
    int rem = i - bh*(c_*c_);
    int cc = rem / c_;
    float s = 0.f;
#pragma unroll
    for (int sk = 0; sk < SPLITK; sk++)
        s += g_kvpart[((size_t)sk*(B_*H_) + bh)*KVPS + rem];
    g_kv[i] = s * g_sinv2[bh*c_ + cc];
}

// ---------------- factor_att: g_attnh = half(scale * q @ kv) ----------------
__global__ __launch_bounds__(256) void k_fact()
{
    extern __shared__ float smf[];
    float* kvs = smf;             // [96][96]
    float* qst = smf + 96*96;     // [96][132]

    int bh = blockIdx.x; int b = bh >> 3, h = bh & 7;
    int n0 = blockIdx.y * 128;
    int tid = threadIdx.x;

    for (int i = tid; i < 96*96; i += 256) kvs[i] = g_kv[(size_t)bh*(c_*c_) + i];
    for (int i = tid; i < 128*96; i += 256) {
        int rr = i / 96, j = i - rr*96;
        int n = n0 + rr;
        float q = 0.f;
        if (n < N_) q = g_qkv[((size_t)(b*N_+n))*QKVC + h*c_ + j];
        qst[j*132 + rr] = q;
    }
    __syncthreads();

    int tx = tid & 15, ty = tid >> 4;
    float acc[8][6];
#pragma unroll
    for (int i = 0; i < 8; i++)
#pragma unroll
        for (int j = 0; j < 6; j++) acc[i][j] = 0.f;

#pragma unroll 2
    for (int k = 0; k < 96; k++) {
        float4 q0 = *(const float4*)&qst[k*132 + ty*8];
        float4 q1 = *(const float4*)&qst[k*132 + ty*8 + 4];
        float2 b0 = *(const float2*)&kvs[k*96 + tx*6];
        float2 b1 = *(const float2*)&kvs[k*96 + tx*6 + 2];
        float2 b2 = *(const float2*)&kvs[k*96 + tx*6 + 4];
        float qa[8] = {q0.x,q0.y,q0.z,q0.w,q1.x,q1.y,q1.z,q1.w};
        float bb[6] = {b0.x,b0.y,b1.x,b1.y,b2.x,b2.y};
#pragma unroll
        for (int i = 0; i < 8; i++)
#pragma unroll
            for (int j = 0; j < 6; j++) acc[i][j] += qa[i]*bb[j];
    }

    const float scale = 0.10206207261596577f;
#pragma unroll
    for (int i = 0; i < 8; i++) {
        int n = n0 + ty*8 + i;
        if (n < N_) {
            __half* o = g_attnh + ((size_t)(b*N_+n))*C_ + h*c_ + tx*6;
            __half2 h0 = __floats2half2_rn(scale*acc[i][0], scale*acc[i][1]);
            __half2 h1 = __floats2half2_rn(scale*acc[i][2], scale*acc[i][3]);
            __half2 h2 = __floats2half2_rn(scale*acc[i][4], scale*acc[i][5]);
            *(__half2*)(o)   = h0;
            *(__half2*)(o+2) = h1;
            *(__half2*)(o+4) = h2;
        }
    }
}

// ---------------- crpe: g_attnh += half(q * (dwconv(v) + bias)) -------------
template <int KSZ>
__global__ __launch_bounds__(256) void k_crpe(const float* __restrict__ w,
                                              const float* __restrict__ bias,
                                              int ch_base)
{
    const int KK = KSZ*KSZ;
    int tile = blockIdx.x;
    int cg   = blockIdx.y;
    int b    = blockIdx.z;
    int ch0  = ch_base + cg*32;
    int ty0  = (tile/7)*8, tx0 = (tile%7)*8;

    __shared__ float wsm[32*49];
    __shared__ float bsm[32];
    __shared__ float patch[196][32];

    int tid = threadIdx.x;
    for (int i = tid; i < 32*KK; i += 256) {
        int chl = i / KK, wi = i - chl*KK;
        wsm[chl*KK + wi] = w[(cg*32 + chl)*KK + wi];
    }
    if (tid < 32) bsm[tid] = bias[cg*32 + tid];

    int lc = tid & 31, lp = tid >> 5;
    for (int p = lp; p < 196; p += 8) {
        int py = p/14 - 3 + ty0, px = p - (p/14)*14 - 3 + tx0;
        float v = 0.f;
        if ((unsigned)py < IMG && (unsigned)px < IMG)
            v = g_qkv[((size_t)(b*N_ + 1 + py*IMG + px))*QKVC + 2*C_ + ch0 + lc];
        patch[p][lc] = v;
    }
    __syncthreads();

    float wr[KK];
#pragma unroll
    for (int i = 0; i < KK; i++) wr[i] = wsm[lc*KK + i];
    float bval = bsm[lc];

    float acc[8];
#pragma unroll
    for (int i = 0; i < 8; i++) acc[i] = 0.f;

    const int pad = KSZ/2, off = 3 - pad;
#pragma unroll
    for (int dy = 0; dy < KSZ; dy++) {
        int prow = (lp + off + dy)*14;
        float r[KSZ + 7];
#pragma unroll
        for (int x = 0; x < KSZ + 7; x++) r[x] = patch[prow + off + x][lc];
#pragma unroll
        for (int ox = 0; ox < 8; ox++)
#pragma unroll
            for (int dx = 0; dx < KSZ; dx++)
                acc[ox] += r[ox+dx]*wr[dy*KSZ+dx];
    }

    int gy = ty0 + lp;
#pragma unroll
    for (int ox = 0; ox < 8; ox++) {
        int gx = tx0 + ox;
        size_t n = (size_t)b*N_ + 1 + gy*IMG + gx;
        float q = g_qkv[n*QKVC + ch0 + lc];
        __half* a = g_attnh + n*C_ + ch0 + lc;
        float cur = __half2float(*a);
        *a = __float2half(cur + q*(acc[ox] + bval));
    }
}

// ---------------- launch ----------------------------------------------------
extern "C" void kernel_launch(void* const* d_in, const int* in_sizes, int n_in,
                              void* d_out, int out_size)
{
    const float* x       = (const float*)d_in[0];
    const float* qkv_w   = (const float*)d_in[1];
    const float* qkv_b   = (const float*)d_in[2];
    const float* proj_w  = (const float*)d_in[3];
    const float* proj_b  = (const float*)d_in[4];
    const float* conv3_w = (const float*)d_in[5];
    const float* conv3_b = (const float*)d_in[6];
    const float* conv5_w = (const float*)d_in[7];
    const float* conv5_b = (const float*)d_in[8];
    const float* conv7_w = (const float*)d_in[9];
    const float* conv7_b = (const float*)d_in[10];

    float*  qkv;   cudaGetSymbolAddress((void**)&qkv,   g_qkv);
    __half* xh;    cudaGetSymbolAddress((void**)&xh,    g_xh);
    __half* attnh; cudaGetSymbolAddress((void**)&attnh, g_attnh);
    __half* qwh;   cudaGetSymbolAddress((void**)&qwh,   g_qkvwh);
    __half* pwh;   cudaGetSymbolAddress((void**)&pwh,   g_projwh);

    const int GEMM_SMEM = NSTAGE * STAGE_BYTES;              // 144 KB
    const int FACT_SMEM = (96*96 + 96*132) * sizeof(float);  // ~85.5 KB

    static bool attr_set = false;
    if (!attr_set) {
        cudaFuncSetAttribute(k_fact, cudaFuncAttributeMaxDynamicSharedMemorySize, FACT_SMEM);
        cudaFuncSetAttribute(gemm_hmma, cudaFuncAttributeMaxDynamicSharedMemorySize, GEMM_SMEM);
        attr_set = true;
    }

    // 0) fp16 copies of GEMM inputs
    f2h_kernel<<<(size_t)(M_*(size_t)C_)/8/256 + 1, 256>>>(x, xh, (size_t)M_*C_);
    f2h_kernel<<<(size_t)(QKVC*(size_t)C_)/8/256 + 1, 256>>>(qkv_w, qwh, (size_t)QKVC*C_);
    f2h_kernel<<<(size_t)(C_*(size_t)C_)/8/256 + 1, 256>>>(proj_w, pwh, (size_t)C_*C_);

    // 1) qkv = x @ qkv_w^T + b   (fp16 mma.sync + cp.async, BK=64)
    gemm_hmma<<<dim3(QKVC/256, (M_+127)/128), 256, GEMM_SMEM>>>(
        xh, qwh, qkv_b, qkv, M_, QKVC, C_);

    // 2) softmax column max over N (sums folded into k_kv)
    k_stats_partial<<<dim3(B_, 3, NCHUNK), 256>>>();
    k_stats_combine<<<(B_*C_ + 255)/256, 256>>>();

    // 3) kv = exp(k-max)^T @ v + column sums  (split-K 16, deterministic)
    k_kv<<<dim3(B_*H_, SPLITK), 256>>>();
    k_sinv<<<(B_*H_*c_ + 255)/256, 256>>>();
    k_kv_reduce<<<(B_*H_*c_*c_ + 255)/256, 256>>>();

    // 4) g_attnh = half(scale * q @ kv)
    k_fact<<<dim3(B_*H_, (N_+127)/128), 256, FACT_SMEM>>>();

    // 5) crpe: g_attnh += half(q * dwconv(v))
    k_crpe<3><<<dim3(49, 6, B_), 256>>>(conv3_w, conv3_b, 0);
    k_crpe<5><<<dim3(49, 9, B_), 256>>>(conv5_w, conv5_b, 192);
    k_crpe<7><<<dim3(49, 9, B_), 256>>>(conv7_w, conv7_b, 480);

    // 6) out = attn @ proj_w^T + proj_b   (fp16 mma.sync + cp.async, BK=64)
    gemm_hmma<<<dim3(C_/256, (M_+127)/128), 256, GEMM_SMEM>>>(
        attnh, pwh, proj_b, (float*)d_out, M_, C_, C_);
}